// round 2
// baseline (speedup 1.0000x reference)
#include <cuda_runtime.h>
#include <math.h>

// Problem constants
#define Bc  2
#define Lc  2048
#define Dc  1024
#define Hc  16
#define Dhc 64
#define Mtot (Bc*Lc)          // 4096
#define Ntot (Hc*Dhc)         // 1024

// Scratch (static device arrays; allocation-free rule)
__device__ float g_Q[Bc*Hc*Lc*Dhc];   // [B,H,L,Dh]
__device__ float g_K[Bc*Hc*Lc*Dhc];   // [B,H,L,Dh]
__device__ float g_V[Bc*Hc*Lc*Dhc];   // [B,H,L,Dh]
__device__ float g_O[Bc*Lc*Hc*Dhc];   // [B,L,H,Dh]  (== [4096,1024] row-major)

// ---------------------------------------------------------------------------
// Fused QKV projection:  x[4096,1024] @ {Wq,Wk,Wv}[1024,1024] -> g_Q/g_K/g_V
// Tiling: BM=64, BN=64, BK=16, 256 threads, 4x4 microtile x 3 weights.
// ---------------------------------------------------------------------------
__global__ __launch_bounds__(256) void qkv_kernel(
    const float* __restrict__ x,
    const float* __restrict__ Wq,
    const float* __restrict__ Wk,
    const float* __restrict__ Wv)
{
    __shared__ float As[16][64];        // As[k][m]
    __shared__ float Bs[3][16][64];     // Bs[w][k][n]

    const int tid = threadIdx.x;
    const int tx  = tid & 15;           // n group
    const int ty  = tid >> 4;           // m group
    const int m0  = blockIdx.y * 64;
    const int n0  = blockIdx.x * 64;

    const float* Ws[3] = {Wq, Wk, Wv};

    float acc[3][16];
#pragma unroll
    for (int w = 0; w < 3; w++)
#pragma unroll
        for (int i = 0; i < 16; i++) acc[w][i] = 0.f;

    const int arow  = tid >> 2;         // 0..63
    const int acol4 = (tid & 3) * 4;    // 0,4,8,12
    const int brow  = tid >> 4;         // 0..15
    const int bcol4 = (tid & 15) * 4;   // 0..60

    for (int k0 = 0; k0 < Dc; k0 += 16) {
        // load A tile 64x16 (transposed into smem)
        float4 av = *(const float4*)&x[(size_t)(m0 + arow) * Dc + k0 + acol4];
        As[acol4 + 0][arow] = av.x;
        As[acol4 + 1][arow] = av.y;
        As[acol4 + 2][arow] = av.z;
        As[acol4 + 3][arow] = av.w;
        // load 3 B tiles 16x64
#pragma unroll
        for (int w = 0; w < 3; w++) {
            float4 bv = *(const float4*)&Ws[w][(size_t)(k0 + brow) * Ntot + n0 + bcol4];
            *(float4*)&Bs[w][brow][bcol4] = bv;
        }
        __syncthreads();

#pragma unroll
        for (int k = 0; k < 16; k++) {
            float4 a4 = *(const float4*)&As[k][ty * 4];
            float a[4] = {a4.x, a4.y, a4.z, a4.w};
#pragma unroll
            for (int w = 0; w < 3; w++) {
                float4 b4 = *(const float4*)&Bs[w][k][tx * 4];
                float b[4] = {b4.x, b4.y, b4.z, b4.w};
#pragma unroll
                for (int i = 0; i < 4; i++)
#pragma unroll
                    for (int j = 0; j < 4; j++)
                        acc[w][i * 4 + j] = fmaf(a[i], b[j], acc[w][i * 4 + j]);
            }
        }
        __syncthreads();
    }

    // write out with [B,H,L,Dh] mapping
#pragma unroll
    for (int i = 0; i < 4; i++) {
        const int mm = m0 + ty * 4 + i;
        const int b  = mm >> 11;            // /L
        const int lq = mm & (Lc - 1);
#pragma unroll
        for (int j = 0; j < 4; j++) {
            const int nn = n0 + tx * 4 + j;
            const int h  = nn >> 6;         // /Dh
            const int e  = nn & (Dhc - 1);
            const size_t idx = ((((size_t)b * Hc + h) * Lc) + lq) * Dhc + e;
            g_Q[idx] = acc[0][i * 4 + j];
            g_K[idx] = acc[1][i * 4 + j];
            g_V[idx] = acc[2][i * 4 + j];
        }
    }
}

// ---------------------------------------------------------------------------
// Causal flash attention, fp32. 64-row Q tile per CTA, 64-row KV tiles.
// 256 threads: tid = r*4 + c4. Thread owns S cols [c4*16, +16) and
// O cols [c4*16, +16) of its row r. Shuffle reductions over 4-lane groups.
// ---------------------------------------------------------------------------
#define ATTN_SMEM (4 * 64 * 65 * 4)

__global__ __launch_bounds__(256) void attn_kernel()
{
    extern __shared__ float sm[];
    float (*Qs)[65] = (float(*)[65])(sm);
    float (*Ks)[65] = (float(*)[65])(sm + 64 * 65);
    float (*Vs)[65] = (float(*)[65])(sm + 2 * 64 * 65);
    float (*Ps)[65] = (float(*)[65])(sm + 3 * 64 * 65);

    const int qt = blockIdx.x;          // q tile 0..31
    const int bh = blockIdx.y;          // 0..31 (b*H + h)
    const int tid = threadIdx.x;
    const int r   = tid >> 2;           // 0..63
    const int c4  = tid & 3;            // 0..3
    const int d0  = c4 * 16;

    const float* Qg = g_Q + (size_t)bh * Lc * Dhc + (size_t)qt * 64 * Dhc;
    const float* Kg = g_K + (size_t)bh * Lc * Dhc;
    const float* Vg = g_V + (size_t)bh * Lc * Dhc;

    // load Q tile
    for (int i = tid; i < 64 * 64; i += 256)
        Qs[i >> 6][i & 63] = Qg[i];

    float mrow = -INFINITY, lrow = 0.f;
    float o[16];
#pragma unroll
    for (int i = 0; i < 16; i++) o[i] = 0.f;

    const float scale = 0.125f;   // 1/sqrt(64)

    for (int j = 0; j <= qt; ++j) {
        const float* Kt = Kg + (size_t)j * 64 * Dhc;
        const float* Vt = Vg + (size_t)j * 64 * Dhc;
        __syncthreads();   // prior-iter smem reads done (also covers Q store, iter 0)
        for (int i = tid; i < 64 * 64; i += 256) {
            Ks[i >> 6][i & 63] = Kt[i];
            Vs[i >> 6][i & 63] = Vt[i];
        }
        __syncthreads();

        // S = Q @ K^T  (this thread: row r, cols d0..d0+15)
        float s[16];
#pragma unroll
        for (int i = 0; i < 16; i++) s[i] = 0.f;
#pragma unroll
        for (int dblk = 0; dblk < 64; dblk += 16) {
            float q[16];
#pragma unroll
            for (int dd = 0; dd < 16; dd++) q[dd] = Qs[r][dblk + dd];
#pragma unroll
            for (int i = 0; i < 16; i++) {
                const int c = d0 + i;
                float acc = s[i];
#pragma unroll
                for (int dd = 0; dd < 16; dd++)
                    acc = fmaf(q[dd], Ks[c][dblk + dd], acc);
                s[i] = acc;
            }
        }

        // scale + causal mask + tile max
        float tmax = -INFINITY;
#pragma unroll
        for (int i = 0; i < 16; i++) {
            s[i] *= scale;
            if (j == qt && (d0 + i) > r) s[i] = -INFINITY;
            tmax = fmaxf(tmax, s[i]);
        }
        tmax = fmaxf(tmax, __shfl_xor_sync(0xffffffffu, tmax, 1));
        tmax = fmaxf(tmax, __shfl_xor_sync(0xffffffffu, tmax, 2));

        const float mnew = fmaxf(mrow, tmax);
        const float corr = __expf(mrow - mnew);
        float psum = 0.f;
#pragma unroll
        for (int i = 0; i < 16; i++) {
            s[i] = __expf(s[i] - mnew);
            psum += s[i];
        }
        psum += __shfl_xor_sync(0xffffffffu, psum, 1);
        psum += __shfl_xor_sync(0xffffffffu, psum, 2);
        lrow = lrow * corr + psum;
        mrow = mnew;
#pragma unroll
        for (int dd = 0; dd < 16; dd++) o[dd] *= corr;

        // stage P, then O += P @ V
#pragma unroll
        for (int i = 0; i < 16; i++) Ps[r][d0 + i] = s[i];
        __syncthreads();
#pragma unroll 4
        for (int c = 0; c < 64; c++) {
            const float p = Ps[r][c];
#pragma unroll
            for (int dd = 0; dd < 16; dd++)
                o[dd] = fmaf(p, Vs[c][d0 + dd], o[dd]);
        }
    }

    // epilogue: normalize, write O in [B,L,H,Dh]
    const float inv = 1.f / lrow;
    const int b = bh >> 4;              // /H
    const int h = bh & (Hc - 1);
    const size_t base = ((((size_t)b * Lc + qt * 64 + r) * Hc) + h) * Dhc + d0;
#pragma unroll
    for (int dd = 0; dd < 16; dd++)
        g_O[base + dd] = o[dd] * inv;
}

// ---------------------------------------------------------------------------
// Output projection: g_O[4096,1024] @ Wout[1024,1024] -> out[4096,1024]
// ---------------------------------------------------------------------------
__global__ __launch_bounds__(256) void proj_kernel(
    const float* __restrict__ Wout,
    float* __restrict__ out)
{
    __shared__ float As[16][64];
    __shared__ float Bs[16][64];

    const int tid = threadIdx.x;
    const int tx  = tid & 15;
    const int ty  = tid >> 4;
    const int m0  = blockIdx.y * 64;
    const int n0  = blockIdx.x * 64;

    float acc[16];
#pragma unroll
    for (int i = 0; i < 16; i++) acc[i] = 0.f;

    const int arow  = tid >> 2;
    const int acol4 = (tid & 3) * 4;
    const int brow  = tid >> 4;
    const int bcol4 = (tid & 15) * 4;

    for (int k0 = 0; k0 < Ntot; k0 += 16) {
        float4 av = *(const float4*)&g_O[(size_t)(m0 + arow) * Ntot + k0 + acol4];
        As[acol4 + 0][arow] = av.x;
        As[acol4 + 1][arow] = av.y;
        As[acol4 + 2][arow] = av.z;
        As[acol4 + 3][arow] = av.w;
        float4 bv = *(const float4*)&Wout[(size_t)(k0 + brow) * Dc + n0 + bcol4];
        *(float4*)&Bs[brow][bcol4] = bv;
        __syncthreads();

#pragma unroll
        for (int k = 0; k < 16; k++) {
            float4 a4 = *(const float4*)&As[k][ty * 4];
            float4 b4 = *(const float4*)&Bs[k][tx * 4];
            float a[4] = {a4.x, a4.y, a4.z, a4.w};
            float b[4] = {b4.x, b4.y, b4.z, b4.w};
#pragma unroll
            for (int i = 0; i < 4; i++)
#pragma unroll
                for (int j = 0; j < 4; j++)
                    acc[i * 4 + j] = fmaf(a[i], b[j], acc[i * 4 + j]);
        }
        __syncthreads();
    }

#pragma unroll
    for (int i = 0; i < 4; i++) {
        const int mm = m0 + ty * 4 + i;
#pragma unroll
        for (int j = 0; j < 4; j++) {
            const int nn = n0 + tx * 4 + j;
            out[(size_t)mm * Dc + nn] = acc[i * 4 + j];
        }
    }
}

// ---------------------------------------------------------------------------
extern "C" void kernel_launch(void* const* d_in, const int* in_sizes, int n_in,
                              void* d_out, int out_size)
{
    (void)in_sizes; (void)n_in; (void)out_size;
    const float* x    = (const float*)d_in[0];
    const float* Wq   = (const float*)d_in[1];
    const float* Wk   = (const float*)d_in[2];
    const float* Wv   = (const float*)d_in[3];
    const float* Wout = (const float*)d_in[4];
    float* out = (float*)d_out;

    cudaFuncSetAttribute(attn_kernel,
                         cudaFuncAttributeMaxDynamicSharedMemorySize, ATTN_SMEM);

    qkv_kernel<<<dim3(Ntot / 64, Mtot / 64), 256>>>(x, Wq, Wk, Wv);
    attn_kernel<<<dim3(Lc / 64, Bc * Hc), 256, ATTN_SMEM>>>();
    proj_kernel<<<dim3(Dc / 64, Mtot / 64), 256>>>(Wout, out);
}

// round 3
// speedup vs baseline: 5.7531x; 5.7531x over previous
#include <cuda_runtime.h>
#include <cuda_bf16.h>
#include <math.h>
#include <stdint.h>

#define Bc 2
#define Lc 2048
#define Dc 1024
#define Hc 16
#define Dhc 64
#define Mtot (Bc*Lc)          // 4096
#define Ntot (Hc*Dhc)         // 1024

typedef __nv_bfloat16 bf16;
typedef __nv_bfloat162 bf162;

// ------------------------- global scratch (no allocs) -----------------------
__device__ bf16 g_xh[Mtot*Dc],  g_xl[Mtot*Dc];
__device__ bf16 g_Wqh[Dc*Ntot], g_Wql[Dc*Ntot];
__device__ bf16 g_Wkh[Dc*Ntot], g_Wkl[Dc*Ntot];
__device__ bf16 g_Wvh[Dc*Ntot], g_Wvl[Dc*Ntot];
__device__ bf16 g_Woh[Dc*Ntot], g_Wol[Dc*Ntot];
__device__ bf16 g_Qh[Bc*Hc*Lc*Dhc], g_Ql[Bc*Hc*Lc*Dhc];   // [B,H,L,Dh]
__device__ bf16 g_Kh[Bc*Hc*Lc*Dhc], g_Kl[Bc*Hc*Lc*Dhc];
__device__ bf16 g_Vh[Bc*Hc*Lc*Dhc], g_Vl[Bc*Hc*Lc*Dhc];
__device__ bf16 g_Oh[Mtot*Dc],  g_Ol[Mtot*Dc];            // [B*L, 1024]

// ------------------------------- helpers ------------------------------------
__device__ __forceinline__ uint32_t smem_u32(const void* p) {
    return (uint32_t)__cvta_generic_to_shared(p);
}
__device__ __forceinline__ void cpa16(void* dst, const void* src) {
    uint32_t d = smem_u32(dst);
    asm volatile("cp.async.cg.shared.global [%0], [%1], 16;\n" :: "r"(d), "l"(src));
}
__device__ __forceinline__ void ldsm4(uint32_t* r, uint32_t a) {
    asm volatile("ldmatrix.sync.aligned.m8n8.x4.shared.b16 {%0,%1,%2,%3}, [%4];\n"
                 : "=r"(r[0]), "=r"(r[1]), "=r"(r[2]), "=r"(r[3]) : "r"(a));
}
__device__ __forceinline__ void ldsm4t(uint32_t* r, uint32_t a) {
    asm volatile("ldmatrix.sync.aligned.m8n8.x4.trans.shared.b16 {%0,%1,%2,%3}, [%4];\n"
                 : "=r"(r[0]), "=r"(r[1]), "=r"(r[2]), "=r"(r[3]) : "r"(a));
}
__device__ __forceinline__ void mma16816(float* c, const uint32_t* a, const uint32_t* b) {
    asm volatile("mma.sync.aligned.m16n8k16.row.col.f32.bf16.bf16.f32 "
                 "{%0,%1,%2,%3}, {%4,%5,%6,%7}, {%8,%9}, {%0,%1,%2,%3};\n"
                 : "+f"(c[0]), "+f"(c[1]), "+f"(c[2]), "+f"(c[3])
                 : "r"(a[0]), "r"(a[1]), "r"(a[2]), "r"(a[3]), "r"(b[0]), "r"(b[1]));
}
__device__ __forceinline__ void split_pack(float x, float y, uint32_t& hi, uint32_t& lo) {
    bf16 xh = __float2bfloat16(x), yh = __float2bfloat16(y);
    bf16 xl = __float2bfloat16(x - __bfloat162float(xh));
    bf16 yl = __float2bfloat16(y - __bfloat162float(yh));
    bf162 h2; h2.x = xh; h2.y = yh;
    bf162 l2; l2.x = xl; l2.y = yl;
    hi = *(uint32_t*)&h2; lo = *(uint32_t*)&l2;
}

// --------------------------- input split kernel -----------------------------
__global__ void split_kernel(const float* __restrict__ src,
                             bf16* __restrict__ hi, bf16* __restrict__ lo, int n) {
    int i = blockIdx.x * blockDim.x + threadIdx.x;
    if (i < n) {
        float v = src[i];
        bf16 h = __float2bfloat16(v);
        hi[i] = h;
        lo[i] = __float2bfloat16(v - __bfloat162float(h));
    }
}

// ------------------------------ GEMM core -----------------------------------
// C[128x128] tile. 256 threads / 8 warps, warp tile 32x64.
// A row-major [M,1024] (hi/lo bf16), B row-major [1024,N] (hi/lo bf16).
// smem halves: sA 2*128*40 per array, sB 2*32*136 per array.
#define GEMM_SMEM_BYTES ((2*128*40*2 + 2*32*136*2) * 2)

__device__ __forceinline__ void gemm_mainloop(
    const bf16* __restrict__ Ah, const bf16* __restrict__ Al,
    const bf16* __restrict__ Bh, const bf16* __restrict__ Bl,
    bf16* sAh, bf16* sAl, bf16* sBh, bf16* sBl,
    int m0, int n0, float acc[2][8][4])
{
    const int tid = threadIdx.x, lane = tid & 31, w = tid >> 5;
    const int wm = w & 3, wn = w >> 2;

#pragma unroll
    for (int mt = 0; mt < 2; mt++)
#pragma unroll
        for (int nt = 0; nt < 8; nt++)
#pragma unroll
            for (int e = 0; e < 4; e++) acc[mt][nt][e] = 0.f;

#define G_LOAD(s, k0g) do{                                                          \
    int r1 = tid >> 2, c1 = (tid & 3) * 8;                                          \
    cpa16(sAh + ((s)*128 + r1)*40 + c1,      Ah + (size_t)(m0 + r1)*Dc + (k0g) + c1);      \
    cpa16(sAh + ((s)*128 + r1 + 64)*40 + c1, Ah + (size_t)(m0 + r1 + 64)*Dc + (k0g) + c1); \
    cpa16(sAl + ((s)*128 + r1)*40 + c1,      Al + (size_t)(m0 + r1)*Dc + (k0g) + c1);      \
    cpa16(sAl + ((s)*128 + r1 + 64)*40 + c1, Al + (size_t)(m0 + r1 + 64)*Dc + (k0g) + c1); \
    int r2 = tid >> 4, c2 = (tid & 15) * 8;                                         \
    cpa16(sBh + ((s)*32 + r2)*136 + c2,      Bh + (size_t)((k0g) + r2)*Ntot + n0 + c2);      \
    cpa16(sBh + ((s)*32 + r2 + 16)*136 + c2, Bh + (size_t)((k0g) + r2 + 16)*Ntot + n0 + c2); \
    cpa16(sBl + ((s)*32 + r2)*136 + c2,      Bl + (size_t)((k0g) + r2)*Ntot + n0 + c2);      \
    cpa16(sBl + ((s)*32 + r2 + 16)*136 + c2, Bl + (size_t)((k0g) + r2 + 16)*Ntot + n0 + c2); \
    asm volatile("cp.async.commit_group;\n" ::); } while(0)

    G_LOAD(0, 0);
    for (int kb = 0; kb < 32; kb++) {
        if (kb < 31) {
            G_LOAD((kb + 1) & 1, (kb + 1) * 32);
            asm volatile("cp.async.wait_group 1;\n" ::: "memory");
        } else {
            asm volatile("cp.async.wait_group 0;\n" ::: "memory");
        }
        __syncthreads();
        const int s = kb & 1;
#pragma unroll
        for (int ks = 0; ks < 2; ks++) {
            uint32_t ah[2][4], al[2][4];
#pragma unroll
            for (int mt = 0; mt < 2; mt++) {
                int row = wm * 32 + mt * 16 + (lane & 15);
                int col = ks * 16 + ((lane >> 4) << 3);
                ldsm4(ah[mt], smem_u32(&sAh[(s * 128 + row) * 40 + col]));
                ldsm4(al[mt], smem_u32(&sAl[(s * 128 + row) * 40 + col]));
            }
#pragma unroll
            for (int np = 0; np < 4; np++) {
                uint32_t bh[4], bl[4];
                int rowb = ks * 16 + (lane & 15);
                int colb = wn * 64 + np * 16 + ((lane >> 4) << 3);
                ldsm4t(bh, smem_u32(&sBh[(s * 32 + rowb) * 136 + colb]));
                ldsm4t(bl, smem_u32(&sBl[(s * 32 + rowb) * 136 + colb]));
#pragma unroll
                for (int mt = 0; mt < 2; mt++) {
                    mma16816(acc[mt][2*np],     ah[mt], &bh[0]);
                    mma16816(acc[mt][2*np],     ah[mt], &bl[0]);
                    mma16816(acc[mt][2*np],     al[mt], &bh[0]);
                    mma16816(acc[mt][2*np + 1], ah[mt], &bh[2]);
                    mma16816(acc[mt][2*np + 1], ah[mt], &bl[2]);
                    mma16816(acc[mt][2*np + 1], al[mt], &bh[2]);
                }
            }
        }
        __syncthreads();
    }
#undef G_LOAD
}

// QKV: x @ {Wq,Wk,Wv} -> Q/K/V hi/lo bf16 in [B,H,L,Dh]
__global__ __launch_bounds__(256) void gemm_qkv_kernel() {
    extern __shared__ bf16 sm[];
    bf16* sAh = sm;
    bf16* sAl = sAh + 2*128*40;
    bf16* sBh = sAl + 2*128*40;
    bf16* sBl = sBh + 2*32*136;

    const int z = blockIdx.z;
    const bf16* Bh = (z == 0) ? g_Wqh : (z == 1) ? g_Wkh : g_Wvh;
    const bf16* Bl = (z == 0) ? g_Wql : (z == 1) ? g_Wkl : g_Wvl;
    bf16* Th = (z == 0) ? g_Qh : (z == 1) ? g_Kh : g_Vh;
    bf16* Tl = (z == 0) ? g_Ql : (z == 1) ? g_Kl : g_Vl;

    const int m0 = blockIdx.y * 128, n0 = blockIdx.x * 128;
    float acc[2][8][4];
    gemm_mainloop(g_xh, g_xl, Bh, Bl, sAh, sAl, sBh, sBl, m0, n0, acc);

    const int lane = threadIdx.x & 31, w = threadIdx.x >> 5;
    const int wm = w & 3, wn = w >> 2;
#pragma unroll
    for (int mt = 0; mt < 2; mt++) {
#pragma unroll
        for (int nt = 0; nt < 8; nt++) {
            int m = m0 + wm * 32 + mt * 16 + (lane >> 2);
            int n = n0 + wn * 64 + nt * 8 + ((lane & 3) << 1);
#pragma unroll
            for (int half = 0; half < 2; half++) {
                int mm = m + half * 8;
                int b = mm >> 11, lq = mm & (Lc - 1);
                int h = n >> 6, e = n & (Dhc - 1);
                size_t idx = ((((size_t)b * Hc + h) * Lc) + lq) * Dhc + e;
                uint32_t hi, lo;
                split_pack(acc[mt][nt][2*half], acc[mt][nt][2*half + 1], hi, lo);
                *(uint32_t*)&Th[idx] = hi;
                *(uint32_t*)&Tl[idx] = lo;
            }
        }
    }
}

// proj: O @ Wout -> out (f32)
__global__ __launch_bounds__(256) void gemm_proj_kernel(float* __restrict__ out) {
    extern __shared__ bf16 sm[];
    bf16* sAh = sm;
    bf16* sAl = sAh + 2*128*40;
    bf16* sBh = sAl + 2*128*40;
    bf16* sBl = sBh + 2*32*136;

    const int m0 = blockIdx.y * 128, n0 = blockIdx.x * 128;
    float acc[2][8][4];
    gemm_mainloop(g_Oh, g_Ol, g_Woh, g_Wol, sAh, sAl, sBh, sBl, m0, n0, acc);

    const int lane = threadIdx.x & 31, w = threadIdx.x >> 5;
    const int wm = w & 3, wn = w >> 2;
#pragma unroll
    for (int mt = 0; mt < 2; mt++) {
#pragma unroll
        for (int nt = 0; nt < 8; nt++) {
            int m = m0 + wm * 32 + mt * 16 + (lane >> 2);
            int n = n0 + wn * 64 + nt * 8 + ((lane & 3) << 1);
            float2 v0 = make_float2(acc[mt][nt][0], acc[mt][nt][1]);
            float2 v1 = make_float2(acc[mt][nt][2], acc[mt][nt][3]);
            *(float2*)&out[(size_t)m * Dc + n]       = v0;
            *(float2*)&out[(size_t)(m + 8) * Dc + n] = v1;
        }
    }
}

// --------------------------- flash attention --------------------------------
// 256 threads / 8 warps. CTA covers 128 q rows (two 64-row subtiles).
// Warp w: subtile sub=w>>2, 16 rows at wq*16 inside it. KV tiles of 64,
// double-buffered via cp.async.
#define ATTN_SMEM_BYTES ((2*128*72 + 4*2*64*72) * 2)

__global__ __launch_bounds__(256) void attn_kernel() {
    extern __shared__ bf16 sm[];
    bf16* sQh = sm;                 // 128*72
    bf16* sQl = sQh + 128*72;
    bf16* sKh = sQl + 128*72;       // 2 stages * 64*72
    bf16* sKl = sKh + 2*64*72;
    bf16* sVh = sKl + 2*64*72;
    bf16* sVl = sVh + 2*64*72;

    const int tid = threadIdx.x, lane = tid & 31, w = tid >> 5;
    const int sub = w >> 2, wq = w & 3;
    const int pair = blockIdx.x, bh = blockIdx.y;
    const int jmax = 2 * pair + 1;
    const int myqt = 2 * pair + sub;
    const size_t base = (size_t)bh * Lc * Dhc;

#define ATT_LOAD(s, j) do{                                                   \
    for (int i = 0; i < 2; i++) {                                            \
        int c = tid + i * 256; int row = c >> 3; int col = (c & 7) * 8;      \
        size_t g = base + ((size_t)(j) * 64 + row) * 64 + col;               \
        size_t so = ((size_t)(s) * 64 + row) * 72 + col;                     \
        cpa16(&sKh[so], &g_Kh[g]); cpa16(&sKl[so], &g_Kl[g]);                \
        cpa16(&sVh[so], &g_Vh[g]); cpa16(&sVl[so], &g_Vl[g]);                \
    }                                                                        \
    asm volatile("cp.async.commit_group;\n" ::); } while(0)

    // load Q tile (128 rows) + prefetch KV tile 0
    {
        const bf16* Qgh = g_Qh + base + (size_t)pair * 128 * 64;
        const bf16* Qgl = g_Ql + base + (size_t)pair * 128 * 64;
        for (int c = tid; c < 1024; c += 256) {
            int row = c >> 3, col = (c & 7) * 8;
            *(uint4*)&sQh[row * 72 + col] = *(const uint4*)&Qgh[row * 64 + col];
            *(uint4*)&sQl[row * 72 + col] = *(const uint4*)&Qgl[row * 64 + col];
        }
    }
    ATT_LOAD(0, 0);
    __syncthreads();

    // Q fragments (held in registers for the whole kernel)
    uint32_t qh[4][4], ql[4][4];
    {
        int row = sub * 64 + wq * 16 + (lane & 15);
#pragma unroll
        for (int ks = 0; ks < 4; ks++) {
            int col = ks * 16 + ((lane >> 4) << 3);
            ldsm4(qh[ks], smem_u32(&sQh[row * 72 + col]));
            ldsm4(ql[ks], smem_u32(&sQl[row * 72 + col]));
        }
    }

    float m0r = -INFINITY, m1r = -INFINITY, l0 = 0.f, l1 = 0.f;
    float oacc[8][4];
#pragma unroll
    for (int nt = 0; nt < 8; nt++)
#pragma unroll
        for (int e = 0; e < 4; e++) oacc[nt][e] = 0.f;

    for (int j = 0; j <= jmax; j++) {
        if (j < jmax) {
            ATT_LOAD((j + 1) & 1, j + 1);
            asm volatile("cp.async.wait_group 1;\n" ::: "memory");
        } else {
            asm volatile("cp.async.wait_group 0;\n" ::: "memory");
        }
        __syncthreads();

        if (j <= myqt) {
            const int s = j & 1;
            float sacc[8][4];
#pragma unroll
            for (int nt = 0; nt < 8; nt++)
#pragma unroll
                for (int e = 0; e < 4; e++) sacc[nt][e] = 0.f;

            // S = Q K^T
#pragma unroll
            for (int ks = 0; ks < 4; ks++) {
#pragma unroll
                for (int np = 0; np < 4; np++) {
                    uint32_t kh[4], kl[4];
                    int rown = np * 16 + ((lane >> 4) << 3) + (lane & 7);
                    int coln = ks * 16 + (lane & 8);
                    ldsm4(kh, smem_u32(&sKh[(s * 64 + rown) * 72 + coln]));
                    ldsm4(kl, smem_u32(&sKl[(s * 64 + rown) * 72 + coln]));
                    mma16816(sacc[2*np],     qh[ks], &kh[0]);
                    mma16816(sacc[2*np],     qh[ks], &kl[0]);
                    mma16816(sacc[2*np],     ql[ks], &kh[0]);
                    mma16816(sacc[2*np + 1], qh[ks], &kh[2]);
                    mma16816(sacc[2*np + 1], qh[ks], &kl[2]);
                    mma16816(sacc[2*np + 1], ql[ks], &kh[2]);
                }
            }

            // scale + causal mask
            const float scale = 0.125f;
            const int r0loc = wq * 16 + (lane >> 2);
            if (j == myqt) {
#pragma unroll
                for (int nt = 0; nt < 8; nt++) {
#pragma unroll
                    for (int e = 0; e < 4; e++) {
                        int c = nt * 8 + ((lane & 3) << 1) + (e & 1);
                        int r = r0loc + ((e >= 2) ? 8 : 0);
                        sacc[nt][e] = (c > r) ? -INFINITY : sacc[nt][e] * scale;
                    }
                }
            } else {
#pragma unroll
                for (int nt = 0; nt < 8; nt++)
#pragma unroll
                    for (int e = 0; e < 4; e++) sacc[nt][e] *= scale;
            }

            // online softmax
            float mx0 = -INFINITY, mx1 = -INFINITY;
#pragma unroll
            for (int nt = 0; nt < 8; nt++) {
                mx0 = fmaxf(mx0, fmaxf(sacc[nt][0], sacc[nt][1]));
                mx1 = fmaxf(mx1, fmaxf(sacc[nt][2], sacc[nt][3]));
            }
            mx0 = fmaxf(mx0, __shfl_xor_sync(0xffffffffu, mx0, 1));
            mx0 = fmaxf(mx0, __shfl_xor_sync(0xffffffffu, mx0, 2));
            mx1 = fmaxf(mx1, __shfl_xor_sync(0xffffffffu, mx1, 1));
            mx1 = fmaxf(mx1, __shfl_xor_sync(0xffffffffu, mx1, 2));

            float mn0 = fmaxf(m0r, mx0), mn1 = fmaxf(m1r, mx1);
            float c0 = __expf(m0r - mn0), c1 = __expf(m1r - mn1);
            float ps0 = 0.f, ps1 = 0.f;
#pragma unroll
            for (int nt = 0; nt < 8; nt++) {
                sacc[nt][0] = __expf(sacc[nt][0] - mn0); ps0 += sacc[nt][0];
                sacc[nt][1] = __expf(sacc[nt][1] - mn0); ps0 += sacc[nt][1];
                sacc[nt][2] = __expf(sacc[nt][2] - mn1); ps1 += sacc[nt][2];
                sacc[nt][3] = __expf(sacc[nt][3] - mn1); ps1 += sacc[nt][3];
            }
            ps0 += __shfl_xor_sync(0xffffffffu, ps0, 1);
            ps0 += __shfl_xor_sync(0xffffffffu, ps0, 2);
            ps1 += __shfl_xor_sync(0xffffffffu, ps1, 1);
            ps1 += __shfl_xor_sync(0xffffffffu, ps1, 2);
            l0 = l0 * c0 + ps0; l1 = l1 * c1 + ps1;
            m0r = mn0; m1r = mn1;
#pragma unroll
            for (int nt = 0; nt < 8; nt++) {
                oacc[nt][0] *= c0; oacc[nt][1] *= c0;
                oacc[nt][2] *= c1; oacc[nt][3] *= c1;
            }

            // pack P into a-fragments (hi/lo)
            uint32_t ph[4][4], pl[4][4];
#pragma unroll
            for (int ks = 0; ks < 4; ks++) {
                int t0 = 2 * ks, t1 = 2 * ks + 1;
                split_pack(sacc[t0][0], sacc[t0][1], ph[ks][0], pl[ks][0]);
                split_pack(sacc[t0][2], sacc[t0][3], ph[ks][1], pl[ks][1]);
                split_pack(sacc[t1][0], sacc[t1][1], ph[ks][2], pl[ks][2]);
                split_pack(sacc[t1][2], sacc[t1][3], ph[ks][3], pl[ks][3]);
            }

            // O += P V
#pragma unroll
            for (int ks = 0; ks < 4; ks++) {
#pragma unroll
                for (int np = 0; np < 4; np++) {
                    uint32_t vh[4], vl[4];
                    int rowv = ks * 16 + (lane & 15);
                    int colv = np * 16 + ((lane >> 4) << 3);
                    ldsm4t(vh, smem_u32(&sVh[(s * 64 + rowv) * 72 + colv]));
                    ldsm4t(vl, smem_u32(&sVl[(s * 64 + rowv) * 72 + colv]));
                    mma16816(oacc[2*np],     ph[ks], &vh[0]);
                    mma16816(oacc[2*np],     ph[ks], &vl[0]);
                    mma16816(oacc[2*np],     pl[ks], &vh[0]);
                    mma16816(oacc[2*np + 1], ph[ks], &vh[2]);
                    mma16816(oacc[2*np + 1], ph[ks], &vl[2]);
                    mma16816(oacc[2*np + 1], pl[ks], &vh[2]);
                }
            }
        }
        __syncthreads();
    }

    // epilogue: O normalized -> g_Oh/g_Ol [B*L, 1024]
    const float inv0 = 1.f / l0, inv1 = 1.f / l1;
    const int b = bh >> 4, hh = bh & (Hc - 1);
    const int mrow0 = pair * 128 + sub * 64 + wq * 16 + (lane >> 2);
#pragma unroll
    for (int nt = 0; nt < 8; nt++) {
        int col = hh * 64 + nt * 8 + ((lane & 3) << 1);
        size_t i0 = ((size_t)b * Lc + mrow0) * Dc + col;
        size_t i1 = ((size_t)b * Lc + mrow0 + 8) * Dc + col;
        uint32_t h01, l01, h23, l23;
        split_pack(oacc[nt][0] * inv0, oacc[nt][1] * inv0, h01, l01);
        split_pack(oacc[nt][2] * inv1, oacc[nt][3] * inv1, h23, l23);
        *(uint32_t*)&g_Oh[i0] = h01; *(uint32_t*)&g_Ol[i0] = l01;
        *(uint32_t*)&g_Oh[i1] = h23; *(uint32_t*)&g_Ol[i1] = l23;
    }
#undef ATT_LOAD
}

// ---------------------------------------------------------------------------
extern "C" void kernel_launch(void* const* d_in, const int* in_sizes, int n_in,
                              void* d_out, int out_size)
{
    (void)in_sizes; (void)n_in; (void)out_size;
    const float* x    = (const float*)d_in[0];
    const float* Wq   = (const float*)d_in[1];
    const float* Wk   = (const float*)d_in[2];
    const float* Wv   = (const float*)d_in[3];
    const float* Wout = (const float*)d_in[4];
    float* out = (float*)d_out;

    void *xh, *xl, *wqh, *wql, *wkh, *wkl, *wvh, *wvl, *woh, *wol;
    cudaGetSymbolAddress(&xh,  g_xh);  cudaGetSymbolAddress(&xl,  g_xl);
    cudaGetSymbolAddress(&wqh, g_Wqh); cudaGetSymbolAddress(&wql, g_Wql);
    cudaGetSymbolAddress(&wkh, g_Wkh); cudaGetSymbolAddress(&wkl, g_Wkl);
    cudaGetSymbolAddress(&wvh, g_Wvh); cudaGetSymbolAddress(&wvl, g_Wvl);
    cudaGetSymbolAddress(&woh, g_Woh); cudaGetSymbolAddress(&wol, g_Wol);

    cudaFuncSetAttribute(gemm_qkv_kernel,
                         cudaFuncAttributeMaxDynamicSharedMemorySize, GEMM_SMEM_BYTES);
    cudaFuncSetAttribute(gemm_proj_kernel,
                         cudaFuncAttributeMaxDynamicSharedMemorySize, GEMM_SMEM_BYTES);
    cudaFuncSetAttribute(attn_kernel,
                         cudaFuncAttributeMaxDynamicSharedMemorySize, ATTN_SMEM_BYTES);

    split_kernel<<<Mtot*Dc/256, 256>>>(x,    (bf16*)xh,  (bf16*)xl,  Mtot*Dc);
    split_kernel<<<Dc*Ntot/256, 256>>>(Wq,   (bf16*)wqh, (bf16*)wql, Dc*Ntot);
    split_kernel<<<Dc*Ntot/256, 256>>>(Wk,   (bf16*)wkh, (bf16*)wkl, Dc*Ntot);
    split_kernel<<<Dc*Ntot/256, 256>>>(Wv,   (bf16*)wvh, (bf16*)wvl, Dc*Ntot);
    split_kernel<<<Dc*Ntot/256, 256>>>(Wout, (bf16*)woh, (bf16*)wol, Dc*Ntot);

    gemm_qkv_kernel<<<dim3(Ntot/128, Mtot/128, 3), 256, GEMM_SMEM_BYTES>>>();
    attn_kernel<<<dim3(Lc/128, Bc*Hc), 256, ATTN_SMEM_BYTES>>>();
    gemm_proj_kernel<<<dim3(Dc/128, Mtot/128), 256, GEMM_SMEM_BYTES>>>(out);
}

// round 9
// speedup vs baseline: 8.4414x; 1.4673x over previous
#include <cuda_runtime.h>
#include <cuda_fp16.h>
#include <math.h>
#include <stdint.h>

#define Bc 2
#define Lc 2048
#define Dc 1024
#define Hc 16
#define Dhc 64
#define Mtot (Bc*Lc)          // 4096
#define Ntot (Hc*Dhc)         // 1024

typedef __half fp16;

// ------------------------- global scratch (no allocs) -----------------------
__device__ fp16 g_xh[Mtot*Dc], g_xl[Mtot*Dc];       // x hi/lo (A side of QKV)
__device__ fp16 g_Wqh[Dc*Ntot];                     // weights: hi only (B side)
__device__ fp16 g_Wkh[Dc*Ntot];
__device__ fp16 g_Wvh[Dc*Ntot];
__device__ fp16 g_Woh[Dc*Ntot];
__device__ fp16 g_Qh[Bc*Hc*Lc*Dhc], g_Ql[Bc*Hc*Lc*Dhc];   // Q hi/lo (A side of S)
__device__ fp16 g_Kh[Bc*Hc*Lc*Dhc];                       // K hi only (B side)
__device__ fp16 g_Vh[Bc*Hc*Lc*Dhc];                       // V hi only (B side)
__device__ fp16 g_Oh[Mtot*Dc], g_Ol[Mtot*Dc];             // attn out hi/lo (A side)

// ------------------------------- helpers ------------------------------------
__device__ __forceinline__ uint32_t smem_u32(const void* p) {
    return (uint32_t)__cvta_generic_to_shared(p);
}
__device__ __forceinline__ void cpa16(void* dst, const void* src) {
    uint32_t d = smem_u32(dst);
    asm volatile("cp.async.cg.shared.global [%0], [%1], 16;\n" :: "r"(d), "l"(src));
}
__device__ __forceinline__ void ldsm4(uint32_t* r, uint32_t a) {
    asm volatile("ldmatrix.sync.aligned.m8n8.x4.shared.b16 {%0,%1,%2,%3}, [%4];\n"
                 : "=r"(r[0]), "=r"(r[1]), "=r"(r[2]), "=r"(r[3]) : "r"(a));
}
__device__ __forceinline__ void ldsm4t(uint32_t* r, uint32_t a) {
    asm volatile("ldmatrix.sync.aligned.m8n8.x4.trans.shared.b16 {%0,%1,%2,%3}, [%4];\n"
                 : "=r"(r[0]), "=r"(r[1]), "=r"(r[2]), "=r"(r[3]) : "r"(a));
}
__device__ __forceinline__ void mma16816(float* c, const uint32_t* a, const uint32_t* b) {
    asm volatile("mma.sync.aligned.m16n8k16.row.col.f32.f16.f16.f32 "
                 "{%0,%1,%2,%3}, {%4,%5,%6,%7}, {%8,%9}, {%0,%1,%2,%3};\n"
                 : "+f"(c[0]), "+f"(c[1]), "+f"(c[2]), "+f"(c[3])
                 : "r"(a[0]), "r"(a[1]), "r"(a[2]), "r"(a[3]), "r"(b[0]), "r"(b[1]));
}
__device__ __forceinline__ void split_pack(float x, float y, uint32_t& hi, uint32_t& lo) {
    __half2 h2 = __floats2half2_rn(x, y);
    float2 hf = __half22float2(h2);
    __half2 l2 = __floats2half2_rn(x - hf.x, y - hf.y);
    hi = *(uint32_t*)&h2; lo = *(uint32_t*)&l2;
}
__device__ __forceinline__ uint32_t pack_h2(float x, float y) {
    __half2 h2 = __floats2half2_rn(x, y);
    return *(uint32_t*)&h2;
}

// --------------------------- input prep kernels -----------------------------
__global__ void split2_kernel(const float4* __restrict__ src,
                              uint2* __restrict__ hi, uint2* __restrict__ lo, int n4) {
    int i = blockIdx.x * blockDim.x + threadIdx.x;
    if (i < n4) {
        float4 v = src[i];
        uint2 h, l;
        split_pack(v.x, v.y, h.x, l.x);
        split_pack(v.z, v.w, h.y, l.y);
        hi[i] = h; lo[i] = l;
    }
}
__global__ void convw_kernel(const float4* __restrict__ src,
                             uint2* __restrict__ dst, int n4) {
    int i = blockIdx.x * blockDim.x + threadIdx.x;
    if (i < n4) {
        float4 v = src[i];
        uint2 h;
        h.x = pack_h2(v.x, v.y);
        h.y = pack_h2(v.z, v.w);
        dst[i] = h;
    }
}

// ------------------------------ GEMM core -----------------------------------
// C[128x128] tile. 256 threads / 8 warps, warp tile 32x64.
// A row-major [M,1024] hi+lo fp16, B row-major [1024,N] hi fp16.
#define GEMM_SMEM_BYTES ((2*128*40*2 + 2*32*136) * 2)

__device__ __forceinline__ void gemm_mainloop(
    const fp16* __restrict__ Ah, const fp16* __restrict__ Al,
    const fp16* __restrict__ Bh,
    fp16* sAh, fp16* sAl, fp16* sBh,
    int m0, int n0, float acc[2][8][4])
{
    const int tid = threadIdx.x, lane = tid & 31, w = tid >> 5;
    const int wm = w & 3, wn = w >> 2;

#pragma unroll
    for (int mt = 0; mt < 2; mt++)
#pragma unroll
        for (int nt = 0; nt < 8; nt++)
#pragma unroll
            for (int e = 0; e < 4; e++) acc[mt][nt][e] = 0.f;

#define G_LOAD(s, k0g) do{                                                          \
    int r1 = tid >> 2, c1 = (tid & 3) * 8;                                          \
    cpa16(sAh + ((s)*128 + r1)*40 + c1,      Ah + (size_t)(m0 + r1)*Dc + (k0g) + c1);      \
    cpa16(sAh + ((s)*128 + r1 + 64)*40 + c1, Ah + (size_t)(m0 + r1 + 64)*Dc + (k0g) + c1); \
    cpa16(sAl + ((s)*128 + r1)*40 + c1,      Al + (size_t)(m0 + r1)*Dc + (k0g) + c1);      \
    cpa16(sAl + ((s)*128 + r1 + 64)*40 + c1, Al + (size_t)(m0 + r1 + 64)*Dc + (k0g) + c1); \
    int r2 = tid >> 4, c2 = (tid & 15) * 8;                                         \
    cpa16(sBh + ((s)*32 + r2)*136 + c2,      Bh + (size_t)((k0g) + r2)*Ntot + n0 + c2);      \
    cpa16(sBh + ((s)*32 + r2 + 16)*136 + c2, Bh + (size_t)((k0g) + r2 + 16)*Ntot + n0 + c2); \
    asm volatile("cp.async.commit_group;\n" ::); } while(0)

    G_LOAD(0, 0);
    for (int kb = 0; kb < 32; kb++) {
        if (kb < 31) {
            G_LOAD((kb + 1) & 1, (kb + 1) * 32);
            asm volatile("cp.async.wait_group 1;\n" ::: "memory");
        } else {
            asm volatile("cp.async.wait_group 0;\n" ::: "memory");
        }
        __syncthreads();
        const int s = kb & 1;
#pragma unroll
        for (int ks = 0; ks < 2; ks++) {
            uint32_t ah[2][4], al[2][4];
#pragma unroll
            for (int mt = 0; mt < 2; mt++) {
                int row = wm * 32 + mt * 16 + (lane & 15);
                int col = ks * 16 + ((lane >> 4) << 3);
                ldsm4(ah[mt], smem_u32(&sAh[(s * 128 + row) * 40 + col]));
                ldsm4(al[mt], smem_u32(&sAl[(s * 128 + row) * 40 + col]));
            }
#pragma unroll
            for (int np = 0; np < 4; np++) {
                uint32_t bh[4];
                int rowb = ks * 16 + (lane & 15);
                int colb = wn * 64 + np * 16 + ((lane >> 4) << 3);
                ldsm4t(bh, smem_u32(&sBh[(s * 32 + rowb) * 136 + colb]));
#pragma unroll
                for (int mt = 0; mt < 2; mt++) {
                    mma16816(acc[mt][2*np],     ah[mt], &bh[0]);
                    mma16816(acc[mt][2*np],     al[mt], &bh[0]);
                    mma16816(acc[mt][2*np + 1], ah[mt], &bh[2]);
                    mma16816(acc[mt][2*np + 1], al[mt], &bh[2]);
                }
            }
        }
        __syncthreads();
    }
#undef G_LOAD
}

// QKV: x @ {Wq,Wk,Wv} -> Q(hi/lo, pre-scaled by 1/8) / K(hi) / V(hi), [B,H,L,Dh]
__global__ __launch_bounds__(256) void gemm_qkv_kernel() {
    extern __shared__ fp16 sm[];
    fp16* sAh = sm;
    fp16* sAl = sAh + 2*128*40;
    fp16* sBh = sAl + 2*128*40;

    const int z = blockIdx.z;
    const fp16* Bh = (z == 0) ? g_Wqh : (z == 1) ? g_Wkh : g_Wvh;
    fp16* Th = (z == 0) ? g_Qh : (z == 1) ? g_Kh : g_Vh;
    const float sc = (z == 0) ? 0.125f : 1.0f;   // fold 1/sqrt(Dh) into Q

    const int m0 = blockIdx.y * 128, n0 = blockIdx.x * 128;
    float acc[2][8][4];
    gemm_mainloop(g_xh, g_xl, Bh, sAh, sAl, sBh, m0, n0, acc);

    const int lane = threadIdx.x & 31, w = threadIdx.x >> 5;
    const int wm = w & 3, wn = w >> 2;
#pragma unroll
    for (int mt = 0; mt < 2; mt++) {
#pragma unroll
        for (int nt = 0; nt < 8; nt++) {
            int m = m0 + wm * 32 + mt * 16 + (lane >> 2);
            int n = n0 + wn * 64 + nt * 8 + ((lane & 3) << 1);
#pragma unroll
            for (int half = 0; half < 2; half++) {
                int mm = m + half * 8;
                int b = mm >> 11, lq = mm & (Lc - 1);
                int h = n >> 6, e = n & (Dhc - 1);
                size_t idx = ((((size_t)b * Hc + h) * Lc) + lq) * Dhc + e;
                float v0 = acc[mt][nt][2*half] * sc;
                float v1 = acc[mt][nt][2*half + 1] * sc;
                if (z == 0) {
                    uint32_t hi, lo;
                    split_pack(v0, v1, hi, lo);
                    *(uint32_t*)&Th[idx] = hi;
                    *(uint32_t*)&g_Ql[idx] = lo;
                } else {
                    *(uint32_t*)&Th[idx] = pack_h2(v0, v1);
                }
            }
        }
    }
}

// proj: g_O(hi/lo) @ Wout(hi) -> out f32
__global__ __launch_bounds__(256) void gemm_proj_kernel(float* __restrict__ out) {
    extern __shared__ fp16 sm[];
    fp16* sAh = sm;
    fp16* sAl = sAh + 2*128*40;
    fp16* sBh = sAl + 2*128*40;

    const int m0 = blockIdx.y * 128, n0 = blockIdx.x * 128;
    float acc[2][8][4];
    gemm_mainloop(g_Oh, g_Ol, g_Woh, sAh, sAl, sBh, m0, n0, acc);

    const int lane = threadIdx.x & 31, w = threadIdx.x >> 5;
    const int wm = w & 3, wn = w >> 2;
#pragma unroll
    for (int mt = 0; mt < 2; mt++) {
#pragma unroll
        for (int nt = 0; nt < 8; nt++) {
            int m = m0 + wm * 32 + mt * 16 + (lane >> 2);
            int n = n0 + wn * 64 + nt * 8 + ((lane & 3) << 1);
            float2 v0 = make_float2(acc[mt][nt][0], acc[mt][nt][1]);
            float2 v1 = make_float2(acc[mt][nt][2], acc[mt][nt][3]);
            *(float2*)&out[(size_t)m * Dc + n]       = v0;
            *(float2*)&out[(size_t)(m + 8) * Dc + n] = v1;
        }
    }
}

// --------------------------- flash attention --------------------------------
// 256 threads / 8 warps. CTA = 128 q rows (two 64-row subtiles).
// Q hi/lo in regs; K,V hi only, double-buffered KV tiles of 64 via cp.async.
#define ATTN_SMEM_BYTES ((2*128*72 + 2*2*64*72) * 2)

__global__ __launch_bounds__(256) void attn_kernel() {
    extern __shared__ fp16 sm[];
    fp16* sQh = sm;                  // 128*72
    fp16* sQl = sQh + 128*72;
    fp16* sKh = sQl + 128*72;        // 2 stages * 64*72
    fp16* sVh = sKh + 2*64*72;

    const int tid = threadIdx.x, lane = tid & 31, w = tid >> 5;
    const int sub = w >> 2, wq = w & 3;
    const int pair = blockIdx.x, bh = blockIdx.y;
    const int jmax = 2 * pair + 1;
    const int myqt = 2 * pair + sub;
    const size_t base = (size_t)bh * Lc * Dhc;

#define ATT_LOAD(s, j) do{                                                   \
    for (int i = 0; i < 2; i++) {                                            \
        int c = tid + i * 256; int row = c >> 3; int col = (c & 7) * 8;      \
        size_t g = base + ((size_t)(j) * 64 + row) * 64 + col;               \
        size_t so = ((size_t)(s) * 64 + row) * 72 + col;                     \
        cpa16(&sKh[so], &g_Kh[g]);                                           \
        cpa16(&sVh[so], &g_Vh[g]);                                           \
    }                                                                        \
    asm volatile("cp.async.commit_group;\n" ::); } while(0)

    {
        const fp16* Qgh = g_Qh + base + (size_t)pair * 128 * 64;
        const fp16* Qgl = g_Ql + base + (size_t)pair * 128 * 64;
        for (int c = tid; c < 1024; c += 256) {
            int row = c >> 3, col = (c & 7) * 8;
            *(uint4*)&sQh[row * 72 + col] = *(const uint4*)&Qgh[row * 64 + col];
            *(uint4*)&sQl[row * 72 + col] = *(const uint4*)&Qgl[row * 64 + col];
        }
    }
    ATT_LOAD(0, 0);
    __syncthreads();

    uint32_t qh[4][4], ql[4][4];
    {
        int row = sub * 64 + wq * 16 + (lane & 15);
#pragma unroll
        for (int ks = 0; ks < 4; ks++) {
            int col = ks * 16 + ((lane >> 4) << 3);
            ldsm4(qh[ks], smem_u32(&sQh[row * 72 + col]));
            ldsm4(ql[ks], smem_u32(&sQl[row * 72 + col]));
        }
    }

    float m0r = -INFINITY, m1r = -INFINITY, l0 = 0.f, l1 = 0.f;
    float oacc[8][4];
#pragma unroll
    for (int nt = 0; nt < 8; nt++)
#pragma unroll
        for (int e = 0; e < 4; e++) oacc[nt][e] = 0.f;

    for (int j = 0; j <= jmax; j++) {
        if (j < jmax) {
            ATT_LOAD((j + 1) & 1, j + 1);
            asm volatile("cp.async.wait_group 1;\n" ::: "memory");
        } else {
            asm volatile("cp.async.wait_group 0;\n" ::: "memory");
        }
        __syncthreads();

        if (j <= myqt) {
            const int s = j & 1;
            float sacc[8][4];
#pragma unroll
            for (int nt = 0; nt < 8; nt++)
#pragma unroll
                for (int e = 0; e < 4; e++) sacc[nt][e] = 0.f;

            // S = Q K^T  (Q pre-scaled)
#pragma unroll
            for (int ks = 0; ks < 4; ks++) {
#pragma unroll
                for (int np = 0; np < 4; np++) {
                    uint32_t kh[4];
                    int rown = np * 16 + ((lane >> 4) << 3) + (lane & 7);
                    int coln = ks * 16 + (lane & 8);
                    ldsm4(kh, smem_u32(&sKh[(s * 64 + rown) * 72 + coln]));
                    mma16816(sacc[2*np],     qh[ks], &kh[0]);
                    mma16816(sacc[2*np],     ql[ks], &kh[0]);
                    mma16816(sacc[2*np + 1], qh[ks], &kh[2]);
                    mma16816(sacc[2*np + 1], ql[ks], &kh[2]);
                }
            }

            // causal mask (diagonal tile only)
            const int r0loc = wq * 16 + (lane >> 2);
            if (j == myqt) {
#pragma unroll
                for (int nt = 0; nt < 8; nt++) {
#pragma unroll
                    for (int e = 0; e < 4; e++) {
                        int c = nt * 8 + ((lane & 3) << 1) + (e & 1);
                        int r = r0loc + ((e >= 2) ? 8 : 0);
                        if (c > r) sacc[nt][e] = -INFINITY;
                    }
                }
            }

            // online softmax
            float mx0 = -INFINITY, mx1 = -INFINITY;
#pragma unroll
            for (int nt = 0; nt < 8; nt++) {
                mx0 = fmaxf(mx0, fmaxf(sacc[nt][0], sacc[nt][1]));
                mx1 = fmaxf(mx1, fmaxf(sacc[nt][2], sacc[nt][3]));
            }
            mx0 = fmaxf(mx0, __shfl_xor_sync(0xffffffffu, mx0, 1));
            mx0 = fmaxf(mx0, __shfl_xor_sync(0xffffffffu, mx0, 2));
            mx1 = fmaxf(mx1, __shfl_xor_sync(0xffffffffu, mx1, 1));
            mx1 = fmaxf(mx1, __shfl_xor_sync(0xffffffffu, mx1, 2));

            float mn0 = fmaxf(m0r, mx0), mn1 = fmaxf(m1r, mx1);
            float c0 = __expf(m0r - mn0), c1 = __expf(m1r - mn1);
            float ps0 = 0.f, ps1 = 0.f;
#pragma unroll
            for (int nt = 0; nt < 8; nt++) {
                sacc[nt][0] = __expf(sacc[nt][0] - mn0); ps0 += sacc[nt][0];
                sacc[nt][1] = __expf(sacc[nt][1] - mn0); ps0 += sacc[nt][1];
                sacc[nt][2] = __expf(sacc[nt][2] - mn1); ps1 += sacc[nt][2];
                sacc[nt][3] = __expf(sacc[nt][3] - mn1); ps1 += sacc[nt][3];
            }
            ps0 += __shfl_xor_sync(0xffffffffu, ps0, 1);
            ps0 += __shfl_xor_sync(0xffffffffu, ps0, 2);
            ps1 += __shfl_xor_sync(0xffffffffu, ps1, 1);
            ps1 += __shfl_xor_sync(0xffffffffu, ps1, 2);
            l0 = l0 * c0 + ps0; l1 = l1 * c1 + ps1;
            m0r = mn0; m1r = mn1;
#pragma unroll
            for (int nt = 0; nt < 8; nt++) {
                oacc[nt][0] *= c0; oacc[nt][1] *= c0;
                oacc[nt][2] *= c1; oacc[nt][3] *= c1;
            }

            // pack P hi/lo into a-fragments
            uint32_t ph[4][4], pl[4][4];
#pragma unroll
            for (int ks = 0; ks < 4; ks++) {
                int t0 = 2 * ks, t1 = 2 * ks + 1;
                split_pack(sacc[t0][0], sacc[t0][1], ph[ks][0], pl[ks][0]);
                split_pack(sacc[t0][2], sacc[t0][3], ph[ks][1], pl[ks][1]);
                split_pack(sacc[t1][0], sacc[t1][1], ph[ks][2], pl[ks][2]);
                split_pack(sacc[t1][2], sacc[t1][3], ph[ks][3], pl[ks][3]);
            }

            // O += P V
#pragma unroll
            for (int ks = 0; ks < 4; ks++) {
#pragma unroll
                for (int np = 0; np < 4; np++) {
                    uint32_t vh[4];
                    int rowv = ks * 16 + (lane & 15);
                    int colv = np * 16 + ((lane >> 4) << 3);
                    ldsm4t(vh, smem_u32(&sVh[(s * 64 + rowv) * 72 + colv]));
                    mma16816(oacc[2*np],     ph[ks], &vh[0]);
                    mma16816(oacc[2*np],     pl[ks], &vh[0]);
                    mma16816(oacc[2*np + 1], ph[ks], &vh[2]);
                    mma16816(oacc[2*np + 1], pl[ks], &vh[2]);
                }
            }
        }
        __syncthreads();
    }

    // epilogue: normalize, split, store O hi/lo as [B*L, 1024]
    const float inv0 = 1.f / l0, inv1 = 1.f / l1;
    const int b = bh >> 4, hh = bh & (Hc - 1);
    const int mrow0 = pair * 128 + sub * 64 + wq * 16 + (lane >> 2);
#pragma unroll
    for (int nt = 0; nt < 8; nt++) {
        int col = hh * 64 + nt * 8 + ((lane & 3) << 1);
        size_t i0 = ((size_t)b * Lc + mrow0) * Dc + col;
        size_t i1 = ((size_t)b * Lc + mrow0 + 8) * Dc + col;
        uint32_t h01, l01, h23, l23;
        split_pack(oacc[nt][0] * inv0, oacc[nt][1] * inv0, h01, l01);
        split_pack(oacc[nt][2] * inv1, oacc[nt][3] * inv1, h23, l23);
        *(uint32_t*)&g_Oh[i0] = h01; *(uint32_t*)&g_Ol[i0] = l01;
        *(uint32_t*)&g_Oh[i1] = h23; *(uint32_t*)&g_Ol[i1] = l23;
    }
#undef ATT_LOAD
}

// ---------------------------------------------------------------------------
extern "C" void kernel_launch(void* const* d_in, const int* in_sizes, int n_in,
                              void* d_out, int out_size)
{
    (void)in_sizes; (void)n_in; (void)out_size;
    const float* x    = (const float*)d_in[0];
    const float* Wq   = (const float*)d_in[1];
    const float* Wk   = (const float*)d_in[2];
    const float* Wv   = (const float*)d_in[3];
    const float* Wout = (const float*)d_in[4];
    float* out = (float*)d_out;

    void *xh, *xl, *wqh, *wkh, *wvh, *woh;
    cudaGetSymbolAddress(&xh,  g_xh);  cudaGetSymbolAddress(&xl, g_xl);
    cudaGetSymbolAddress(&wqh, g_Wqh); cudaGetSymbolAddress(&wkh, g_Wkh);
    cudaGetSymbolAddress(&wvh, g_Wvh); cudaGetSymbolAddress(&woh, g_Woh);

    cudaFuncSetAttribute(gemm_qkv_kernel,
                         cudaFuncAttributeMaxDynamicSharedMemorySize, GEMM_SMEM_BYTES);
    cudaFuncSetAttribute(gemm_proj_kernel,
                         cudaFuncAttributeMaxDynamicSharedMemorySize, GEMM_SMEM_BYTES);
    cudaFuncSetAttribute(attn_kernel,
                         cudaFuncAttributeMaxDynamicSharedMemorySize, ATTN_SMEM_BYTES);

    split2_kernel<<<Mtot*Dc/4/256, 256>>>((const float4*)x, (uint2*)xh, (uint2*)xl, Mtot*Dc/4);
    convw_kernel<<<Dc*Ntot/4/256, 256>>>((const float4*)Wq,   (uint2*)wqh, Dc*Ntot/4);
    convw_kernel<<<Dc*Ntot/4/256, 256>>>((const float4*)Wk,   (uint2*)wkh, Dc*Ntot/4);
    convw_kernel<<<Dc*Ntot/4/256, 256>>>((const float4*)Wv,   (uint2*)wvh, Dc*Ntot/4);
    convw_kernel<<<Dc*Ntot/4/256, 256>>>((const float4*)Wout, (uint2*)woh, Dc*Ntot/4);

    gemm_qkv_kernel<<<dim3(Ntot/128, Mtot/128, 3), 256, GEMM_SMEM_BYTES>>>();
    attn_kernel<<<dim3(Lc/128, Bc*Hc), 256, ATTN_SMEM_BYTES>>>();
    gemm_proj_kernel<<<dim3(Dc/128, Mtot/128), 256, GEMM_SMEM_BYTES>>>(out);
}

// round 10
// speedup vs baseline: 8.9861x; 1.0645x over previous
#include <cuda_runtime.h>
#include <cuda_fp16.h>
#include <math.h>
#include <stdint.h>

#define Bc 2
#define Lc 2048
#define Dc 1024
#define Hc 16
#define Dhc 64
#define Mtot (Bc*Lc)          // 4096
#define Ntot (Hc*Dhc)         // 1024

typedef __half fp16;

// ------------------------- global scratch (no allocs) -----------------------
__device__ fp16 g_xh[Mtot*Dc], g_xl[Mtot*Dc];       // x hi/lo (A side of QKV)
__device__ fp16 g_Wqh[Dc*Ntot];                     // weights: hi only (B side)
__device__ fp16 g_Wkh[Dc*Ntot];
__device__ fp16 g_Wvh[Dc*Ntot];
__device__ fp16 g_Woh[Dc*Ntot];
__device__ fp16 g_Qh[Bc*Hc*Lc*Dhc], g_Ql[Bc*Hc*Lc*Dhc];   // Q hi/lo (A side of S)
__device__ fp16 g_Kh[Bc*Hc*Lc*Dhc];                       // K hi only (B side)
__device__ fp16 g_Vh[Bc*Hc*Lc*Dhc];                       // V hi only (B side)
__device__ fp16 g_Oh[Mtot*Dc], g_Ol[Mtot*Dc];             // attn out hi/lo (A side)

// ------------------------------- helpers ------------------------------------
__device__ __forceinline__ uint32_t smem_u32(const void* p) {
    return (uint32_t)__cvta_generic_to_shared(p);
}
__device__ __forceinline__ void cpa16(void* dst, const void* src) {
    uint32_t d = smem_u32(dst);
    asm volatile("cp.async.cg.shared.global [%0], [%1], 16;\n" :: "r"(d), "l"(src));
}
__device__ __forceinline__ void ldsm4(uint32_t* r, uint32_t a) {
    asm volatile("ldmatrix.sync.aligned.m8n8.x4.shared.b16 {%0,%1,%2,%3}, [%4];\n"
                 : "=r"(r[0]), "=r"(r[1]), "=r"(r[2]), "=r"(r[3]) : "r"(a));
}
__device__ __forceinline__ void ldsm4t(uint32_t* r, uint32_t a) {
    asm volatile("ldmatrix.sync.aligned.m8n8.x4.trans.shared.b16 {%0,%1,%2,%3}, [%4];\n"
                 : "=r"(r[0]), "=r"(r[1]), "=r"(r[2]), "=r"(r[3]) : "r"(a));
}
__device__ __forceinline__ void mma16816(float* c, const uint32_t* a, const uint32_t* b) {
    asm volatile("mma.sync.aligned.m16n8k16.row.col.f32.f16.f16.f32 "
                 "{%0,%1,%2,%3}, {%4,%5,%6,%7}, {%8,%9}, {%0,%1,%2,%3};\n"
                 : "+f"(c[0]), "+f"(c[1]), "+f"(c[2]), "+f"(c[3])
                 : "r"(a[0]), "r"(a[1]), "r"(a[2]), "r"(a[3]), "r"(b[0]), "r"(b[1]));
}
__device__ __forceinline__ void split_pack(float x, float y, uint32_t& hi, uint32_t& lo) {
    __half2 h2 = __floats2half2_rn(x, y);
    float2 hf = __half22float2(h2);
    __half2 l2 = __floats2half2_rn(x - hf.x, y - hf.y);
    hi = *(uint32_t*)&h2; lo = *(uint32_t*)&l2;
}
__device__ __forceinline__ uint32_t pack_h2(float x, float y) {
    __half2 h2 = __floats2half2_rn(x, y);
    return *(uint32_t*)&h2;
}

// --------------------------- input prep kernels -----------------------------
__global__ void split2_kernel(const float4* __restrict__ src,
                              uint2* __restrict__ hi, uint2* __restrict__ lo, int n4) {
    int i = blockIdx.x * blockDim.x + threadIdx.x;
    if (i < n4) {
        float4 v = src[i];
        uint2 h, l;
        split_pack(v.x, v.y, h.x, l.x);
        split_pack(v.z, v.w, h.y, l.y);
        hi[i] = h; lo[i] = l;
    }
}
// all 4 weight conversions in one launch (blockIdx.y selects tensor)
__global__ void convw4_kernel(const float4* __restrict__ s0, const float4* __restrict__ s1,
                              const float4* __restrict__ s2, const float4* __restrict__ s3,
                              uint2* __restrict__ d0, uint2* __restrict__ d1,
                              uint2* __restrict__ d2, uint2* __restrict__ d3, int n4) {
    const int z = blockIdx.y;
    const float4* s = (z == 0) ? s0 : (z == 1) ? s1 : (z == 2) ? s2 : s3;
    uint2* d = (z == 0) ? d0 : (z == 1) ? d1 : (z == 2) ? d2 : d3;
    int i = blockIdx.x * blockDim.x + threadIdx.x;
    if (i < n4) {
        float4 v = s[i];
        uint2 h;
        h.x = pack_h2(v.x, v.y);
        h.y = pack_h2(v.z, v.w);
        d[i] = h;
    }
}

// ------------------------------ GEMM core -----------------------------------
// C[128x128] tile. 256 threads / 8 warps, warp tile 32x64.
// A row-major [M,1024] hi+lo fp16, B row-major [1024,N] hi fp16.
// 3-stage cp.async pipeline, single __syncthreads per K-iteration.
#define GEMM_SMEM_BYTES ((3*128*40*2 + 3*32*136) * 2)

__device__ __forceinline__ void gemm_mainloop(
    const fp16* __restrict__ Ah, const fp16* __restrict__ Al,
    const fp16* __restrict__ Bh,
    fp16* sAh, fp16* sAl, fp16* sBh,
    int m0, int n0, float acc[2][8][4])
{
    const int tid = threadIdx.x, lane = tid & 31, w = tid >> 5;
    const int wm = w & 3, wn = w >> 2;

#pragma unroll
    for (int mt = 0; mt < 2; mt++)
#pragma unroll
        for (int nt = 0; nt < 8; nt++)
#pragma unroll
            for (int e = 0; e < 4; e++) acc[mt][nt][e] = 0.f;

#define G_LOAD(s, k0g) do{                                                          \
    int r1 = tid >> 2, c1 = (tid & 3) * 8;                                          \
    cpa16(sAh + ((s)*128 + r1)*40 + c1,      Ah + (size_t)(m0 + r1)*Dc + (k0g) + c1);      \
    cpa16(sAh + ((s)*128 + r1 + 64)*40 + c1, Ah + (size_t)(m0 + r1 + 64)*Dc + (k0g) + c1); \
    cpa16(sAl + ((s)*128 + r1)*40 + c1,      Al + (size_t)(m0 + r1)*Dc + (k0g) + c1);      \
    cpa16(sAl + ((s)*128 + r1 + 64)*40 + c1, Al + (size_t)(m0 + r1 + 64)*Dc + (k0g) + c1); \
    int r2 = tid >> 4, c2 = (tid & 15) * 8;                                         \
    cpa16(sBh + ((s)*32 + r2)*136 + c2,      Bh + (size_t)((k0g) + r2)*Ntot + n0 + c2);      \
    cpa16(sBh + ((s)*32 + r2 + 16)*136 + c2, Bh + (size_t)((k0g) + r2 + 16)*Ntot + n0 + c2); \
    asm volatile("cp.async.commit_group;\n" ::); } while(0)

    G_LOAD(0, 0);
    G_LOAD(1, 32);
    int s = 0;
    for (int kb = 0; kb < 32; kb++) {
        if (kb < 31) asm volatile("cp.async.wait_group 1;\n" ::: "memory");
        else         asm volatile("cp.async.wait_group 0;\n" ::: "memory");
        __syncthreads();
        if (kb + 2 < 32) {
            int sn = s + 2; if (sn >= 3) sn -= 3;
            G_LOAD(sn, (kb + 2) * 32);
        }
#pragma unroll
        for (int ks = 0; ks < 2; ks++) {
            uint32_t ah[2][4], al[2][4];
#pragma unroll
            for (int mt = 0; mt < 2; mt++) {
                int row = wm * 32 + mt * 16 + (lane & 15);
                int col = ks * 16 + ((lane >> 4) << 3);
                ldsm4(ah[mt], smem_u32(&sAh[(s * 128 + row) * 40 + col]));
                ldsm4(al[mt], smem_u32(&sAl[(s * 128 + row) * 40 + col]));
            }
#pragma unroll
            for (int np = 0; np < 4; np++) {
                uint32_t bh[4];
                int rowb = ks * 16 + (lane & 15);
                int colb = wn * 64 + np * 16 + ((lane >> 4) << 3);
                ldsm4t(bh, smem_u32(&sBh[(s * 32 + rowb) * 136 + colb]));
#pragma unroll
                for (int mt = 0; mt < 2; mt++) {
                    mma16816(acc[mt][2*np],     ah[mt], &bh[0]);
                    mma16816(acc[mt][2*np],     al[mt], &bh[0]);
                    mma16816(acc[mt][2*np + 1], ah[mt], &bh[2]);
                    mma16816(acc[mt][2*np + 1], al[mt], &bh[2]);
                }
            }
        }
        if (++s >= 3) s = 0;
    }
#undef G_LOAD
}

// QKV: x @ {Wq,Wk,Wv} -> Q(hi/lo, pre-scaled by 1/8) / K(hi) / V(hi), [B,H,L,Dh]
__global__ __launch_bounds__(256) void gemm_qkv_kernel() {
    extern __shared__ fp16 sm[];
    fp16* sAh = sm;
    fp16* sAl = sAh + 3*128*40;
    fp16* sBh = sAl + 3*128*40;

    const int z = blockIdx.z;
    const fp16* Bh = (z == 0) ? g_Wqh : (z == 1) ? g_Wkh : g_Wvh;
    fp16* Th = (z == 0) ? g_Qh : (z == 1) ? g_Kh : g_Vh;
    const float sc = (z == 0) ? 0.125f : 1.0f;   // fold 1/sqrt(Dh) into Q

    const int m0 = blockIdx.y * 128, n0 = blockIdx.x * 128;
    float acc[2][8][4];
    gemm_mainloop(g_xh, g_xl, Bh, sAh, sAl, sBh, m0, n0, acc);

    const int lane = threadIdx.x & 31, w = threadIdx.x >> 5;
    const int wm = w & 3, wn = w >> 2;
#pragma unroll
    for (int mt = 0; mt < 2; mt++) {
#pragma unroll
        for (int nt = 0; nt < 8; nt++) {
            int m = m0 + wm * 32 + mt * 16 + (lane >> 2);
            int n = n0 + wn * 64 + nt * 8 + ((lane & 3) << 1);
#pragma unroll
            for (int half = 0; half < 2; half++) {
                int mm = m + half * 8;
                int b = mm >> 11, lq = mm & (Lc - 1);
                int h = n >> 6, e = n & (Dhc - 1);
                size_t idx = ((((size_t)b * Hc + h) * Lc) + lq) * Dhc + e;
                float v0 = acc[mt][nt][2*half] * sc;
                float v1 = acc[mt][nt][2*half + 1] * sc;
                if (z == 0) {
                    uint32_t hi, lo;
                    split_pack(v0, v1, hi, lo);
                    *(uint32_t*)&Th[idx] = hi;
                    *(uint32_t*)&g_Ql[idx] = lo;
                } else {
                    *(uint32_t*)&Th[idx] = pack_h2(v0, v1);
                }
            }
        }
    }
}

// proj: g_O(hi/lo) @ Wout(hi) -> out f32
__global__ __launch_bounds__(256) void gemm_proj_kernel(float* __restrict__ out) {
    extern __shared__ fp16 sm[];
    fp16* sAh = sm;
    fp16* sAl = sAh + 3*128*40;
    fp16* sBh = sAl + 3*128*40;

    const int m0 = blockIdx.y * 128, n0 = blockIdx.x * 128;
    float acc[2][8][4];
    gemm_mainloop(g_Oh, g_Ol, g_Woh, sAh, sAl, sBh, m0, n0, acc);

    const int lane = threadIdx.x & 31, w = threadIdx.x >> 5;
    const int wm = w & 3, wn = w >> 2;
#pragma unroll
    for (int mt = 0; mt < 2; mt++) {
#pragma unroll
        for (int nt = 0; nt < 8; nt++) {
            int m = m0 + wm * 32 + mt * 16 + (lane >> 2);
            int n = n0 + wn * 64 + nt * 8 + ((lane & 3) << 1);
            float2 v0 = make_float2(acc[mt][nt][0], acc[mt][nt][1]);
            float2 v1 = make_float2(acc[mt][nt][2], acc[mt][nt][3]);
            *(float2*)&out[(size_t)m * Dc + n]       = v0;
            *(float2*)&out[(size_t)(m + 8) * Dc + n] = v1;
        }
    }
}

// --------------------------- flash attention --------------------------------
// 256 threads / 8 warps. CTA = 128 q rows (two 64-row subtiles).
// Q hi/lo in regs; K,V hi only; 3-stage cp.async KV pipeline, 1 sync/iter.
#define ATTN_SMEM_BYTES ((2*128*72 + 2*3*64*72) * 2)

__global__ __launch_bounds__(256) void attn_kernel() {
    extern __shared__ fp16 sm[];
    fp16* sQh = sm;                  // 128*72
    fp16* sQl = sQh + 128*72;
    fp16* sKh = sQl + 128*72;        // 3 stages * 64*72
    fp16* sVh = sKh + 3*64*72;

    const int tid = threadIdx.x, lane = tid & 31, w = tid >> 5;
    const int sub = w >> 2, wq = w & 3;
    const int pair = (int)(gridDim.x - 1 - blockIdx.x);   // heavy tiles first
    const int bh = blockIdx.y;
    const int jmax = 2 * pair + 1;
    const int myqt = 2 * pair + sub;
    const size_t base = (size_t)bh * Lc * Dhc;

#define ATT_LOAD(s, j) do{                                                   \
    for (int i = 0; i < 2; i++) {                                            \
        int c = tid + i * 256; int row = c >> 3; int col = (c & 7) * 8;      \
        size_t g = base + ((size_t)(j) * 64 + row) * 64 + col;               \
        size_t so = ((size_t)(s) * 64 + row) * 72 + col;                     \
        cpa16(&sKh[so], &g_Kh[g]);                                           \
        cpa16(&sVh[so], &g_Vh[g]);                                           \
    }                                                                        \
    asm volatile("cp.async.commit_group;\n" ::); } while(0)

    {
        const fp16* Qgh = g_Qh + base + (size_t)pair * 128 * 64;
        const fp16* Qgl = g_Ql + base + (size_t)pair * 128 * 64;
        for (int c = tid; c < 1024; c += 256) {
            int row = c >> 3, col = (c & 7) * 8;
            *(uint4*)&sQh[row * 72 + col] = *(const uint4*)&Qgh[row * 64 + col];
            *(uint4*)&sQl[row * 72 + col] = *(const uint4*)&Qgl[row * 64 + col];
        }
    }
    ATT_LOAD(0, 0);
    ATT_LOAD(1, 1);                  // jmax >= 1 always
    __syncthreads();

    uint32_t qh[4][4], ql[4][4];
    {
        int row = sub * 64 + wq * 16 + (lane & 15);
#pragma unroll
        for (int ks = 0; ks < 4; ks++) {
            int col = ks * 16 + ((lane >> 4) << 3);
            ldsm4(qh[ks], smem_u32(&sQh[row * 72 + col]));
            ldsm4(ql[ks], smem_u32(&sQl[row * 72 + col]));
        }
    }

    float m0r = -INFINITY, m1r = -INFINITY, l0 = 0.f, l1 = 0.f;
    float oacc[8][4];
#pragma unroll
    for (int nt = 0; nt < 8; nt++)
#pragma unroll
        for (int e = 0; e < 4; e++) oacc[nt][e] = 0.f;

    int s = 0;
    for (int j = 0; j <= jmax; j++) {
        if (j < jmax) asm volatile("cp.async.wait_group 1;\n" ::: "memory");
        else          asm volatile("cp.async.wait_group 0;\n" ::: "memory");
        __syncthreads();
        if (j + 2 <= jmax) {
            int sn = s + 2; if (sn >= 3) sn -= 3;
            ATT_LOAD(sn, j + 2);
        }

        if (j <= myqt) {
            float sacc[8][4];
#pragma unroll
            for (int nt = 0; nt < 8; nt++)
#pragma unroll
                for (int e = 0; e < 4; e++) sacc[nt][e] = 0.f;

            // S = Q K^T  (Q pre-scaled)
#pragma unroll
            for (int ks = 0; ks < 4; ks++) {
#pragma unroll
                for (int np = 0; np < 4; np++) {
                    uint32_t kh[4];
                    int rown = np * 16 + ((lane >> 4) << 3) + (lane & 7);
                    int coln = ks * 16 + (lane & 8);
                    ldsm4(kh, smem_u32(&sKh[(s * 64 + rown) * 72 + coln]));
                    mma16816(sacc[2*np],     qh[ks], &kh[0]);
                    mma16816(sacc[2*np],     ql[ks], &kh[0]);
                    mma16816(sacc[2*np + 1], qh[ks], &kh[2]);
                    mma16816(sacc[2*np + 1], ql[ks], &kh[2]);
                }
            }

            // causal mask (diagonal tile only)
            const int r0loc = wq * 16 + (lane >> 2);
            if (j == myqt) {
#pragma unroll
                for (int nt = 0; nt < 8; nt++) {
#pragma unroll
                    for (int e = 0; e < 4; e++) {
                        int c = nt * 8 + ((lane & 3) << 1) + (e & 1);
                        int r = r0loc + ((e >= 2) ? 8 : 0);
                        if (c > r) sacc[nt][e] = -INFINITY;
                    }
                }
            }

            // online softmax
            float mx0 = -INFINITY, mx1 = -INFINITY;
#pragma unroll
            for (int nt = 0; nt < 8; nt++) {
                mx0 = fmaxf(mx0, fmaxf(sacc[nt][0], sacc[nt][1]));
                mx1 = fmaxf(mx1, fmaxf(sacc[nt][2], sacc[nt][3]));
            }
            mx0 = fmaxf(mx0, __shfl_xor_sync(0xffffffffu, mx0, 1));
            mx0 = fmaxf(mx0, __shfl_xor_sync(0xffffffffu, mx0, 2));
            mx1 = fmaxf(mx1, __shfl_xor_sync(0xffffffffu, mx1, 1));
            mx1 = fmaxf(mx1, __shfl_xor_sync(0xffffffffu, mx1, 2));

            float mn0 = fmaxf(m0r, mx0), mn1 = fmaxf(m1r, mx1);
            float c0 = __expf(m0r - mn0), c1 = __expf(m1r - mn1);
            float ps0 = 0.f, ps1 = 0.f;
#pragma unroll
            for (int nt = 0; nt < 8; nt++) {
                sacc[nt][0] = __expf(sacc[nt][0] - mn0); ps0 += sacc[nt][0];
                sacc[nt][1] = __expf(sacc[nt][1] - mn0); ps0 += sacc[nt][1];
                sacc[nt][2] = __expf(sacc[nt][2] - mn1); ps1 += sacc[nt][2];
                sacc[nt][3] = __expf(sacc[nt][3] - mn1); ps1 += sacc[nt][3];
            }
            ps0 += __shfl_xor_sync(0xffffffffu, ps0, 1);
            ps0 += __shfl_xor_sync(0xffffffffu, ps0, 2);
            ps1 += __shfl_xor_sync(0xffffffffu, ps1, 1);
            ps1 += __shfl_xor_sync(0xffffffffu, ps1, 2);
            l0 = l0 * c0 + ps0; l1 = l1 * c1 + ps1;
            m0r = mn0; m1r = mn1;
#pragma unroll
            for (int nt = 0; nt < 8; nt++) {
                oacc[nt][0] *= c0; oacc[nt][1] *= c0;
                oacc[nt][2] *= c1; oacc[nt][3] *= c1;
            }

            // pack P hi/lo into a-fragments
            uint32_t ph[4][4], pl[4][4];
#pragma unroll
            for (int ks = 0; ks < 4; ks++) {
                int t0 = 2 * ks, t1 = 2 * ks + 1;
                split_pack(sacc[t0][0], sacc[t0][1], ph[ks][0], pl[ks][0]);
                split_pack(sacc[t0][2], sacc[t0][3], ph[ks][1], pl[ks][1]);
                split_pack(sacc[t1][0], sacc[t1][1], ph[ks][2], pl[ks][2]);
                split_pack(sacc[t1][2], sacc[t1][3], ph[ks][3], pl[ks][3]);
            }

            // O += P V
#pragma unroll
            for (int ks = 0; ks < 4; ks++) {
#pragma unroll
                for (int np = 0; np < 4; np++) {
                    uint32_t vh[4];
                    int rowv = ks * 16 + (lane & 15);
                    int colv = np * 16 + ((lane >> 4) << 3);
                    ldsm4t(vh, smem_u32(&sVh[(s * 64 + rowv) * 72 + colv]));
                    mma16816(oacc[2*np],     ph[ks], &vh[0]);
                    mma16816(oacc[2*np],     pl[ks], &vh[0]);
                    mma16816(oacc[2*np + 1], ph[ks], &vh[2]);
                    mma16816(oacc[2*np + 1], pl[ks], &vh[2]);
                }
            }
        }
        if (++s >= 3) s = 0;
    }

    // epilogue: normalize, split, store O hi/lo as [B*L, 1024]
    const float inv0 = 1.f / l0, inv1 = 1.f / l1;
    const int b = bh >> 4, hh = bh & (Hc - 1);
    const int mrow0 = pair * 128 + sub * 64 + wq * 16 + (lane >> 2);
#pragma unroll
    for (int nt = 0; nt < 8; nt++) {
        int col = hh * 64 + nt * 8 + ((lane & 3) << 1);
        size_t i0 = ((size_t)b * Lc + mrow0) * Dc + col;
        size_t i1 = ((size_t)b * Lc + mrow0 + 8) * Dc + col;
        uint32_t h01, l01, h23, l23;
        split_pack(oacc[nt][0] * inv0, oacc[nt][1] * inv0, h01, l01);
        split_pack(oacc[nt][2] * inv1, oacc[nt][3] * inv1, h23, l23);
        *(uint32_t*)&g_Oh[i0] = h01; *(uint32_t*)&g_Ol[i0] = l01;
        *(uint32_t*)&g_Oh[i1] = h23; *(uint32_t*)&g_Ol[i1] = l23;
    }
#undef ATT_LOAD
}

// ---------------------------------------------------------------------------
extern "C" void kernel_launch(void* const* d_in, const int* in_sizes, int n_in,
                              void* d_out, int out_size)
{
    (void)in_sizes; (void)n_in; (void)out_size;
    const float* x    = (const float*)d_in[0];
    const float* Wq   = (const float*)d_in[1];
    const float* Wk   = (const float*)d_in[2];
    const float* Wv   = (const float*)d_in[3];
    const float* Wout = (const float*)d_in[4];
    float* out = (float*)d_out;

    void *xh, *xl, *wqh, *wkh, *wvh, *woh;
    cudaGetSymbolAddress(&xh,  g_xh);  cudaGetSymbolAddress(&xl, g_xl);
    cudaGetSymbolAddress(&wqh, g_Wqh); cudaGetSymbolAddress(&wkh, g_Wkh);
    cudaGetSymbolAddress(&wvh, g_Wvh); cudaGetSymbolAddress(&woh, g_Woh);

    cudaFuncSetAttribute(gemm_qkv_kernel,
                         cudaFuncAttributeMaxDynamicSharedMemorySize, GEMM_SMEM_BYTES);
    cudaFuncSetAttribute(gemm_proj_kernel,
                         cudaFuncAttributeMaxDynamicSharedMemorySize, GEMM_SMEM_BYTES);
    cudaFuncSetAttribute(attn_kernel,
                         cudaFuncAttributeMaxDynamicSharedMemorySize, ATTN_SMEM_BYTES);

    split2_kernel<<<Mtot*Dc/4/256, 256>>>((const float4*)x, (uint2*)xh, (uint2*)xl, Mtot*Dc/4);
    convw4_kernel<<<dim3(Dc*Ntot/4/256, 4), 256>>>(
        (const float4*)Wq, (const float4*)Wk, (const float4*)Wv, (const float4*)Wout,
        (uint2*)wqh, (uint2*)wkh, (uint2*)wvh, (uint2*)woh, Dc*Ntot/4);

    gemm_qkv_kernel<<<dim3(Ntot/128, Mtot/128, 3), 256, GEMM_SMEM_BYTES>>>();
    attn_kernel<<<dim3(Lc/128, Bc*Hc), 256, ATTN_SMEM_BYTES>>>();
    gemm_proj_kernel<<<dim3(Dc/128, Mtot/128), 256, GEMM_SMEM_BYTES>>>(out);
}

// round 13
// speedup vs baseline: 9.4119x; 1.0474x over previous
#include <cuda_runtime.h>
#include <cuda_fp16.h>
#include <math.h>
#include <stdint.h>

#define Bc 2
#define Lc 2048
#define Dc 1024
#define Hc 16
#define Dhc 64
#define Mtot (Bc*Lc)          // 4096
#define Ntot (Hc*Dhc)         // 1024

typedef __half fp16;

// ------------------------- global scratch (no allocs) -----------------------
__device__ fp16 g_xh[Mtot*Dc], g_xl[Mtot*Dc];       // x hi/lo (A side of QKV)
__device__ fp16 g_Wqh[Dc*Ntot];                     // weights: hi only (B side)
__device__ fp16 g_Wkh[Dc*Ntot];
__device__ fp16 g_Wvh[Dc*Ntot];
__device__ fp16 g_Woh[Dc*Ntot];
__device__ fp16 g_Qh[Bc*Hc*Lc*Dhc], g_Ql[Bc*Hc*Lc*Dhc];   // Q hi/lo (A side of S)
__device__ fp16 g_Kh[Bc*Hc*Lc*Dhc];                       // K hi only (B side)
__device__ fp16 g_Vh[Bc*Hc*Lc*Dhc];                       // V hi only (B side)
__device__ fp16 g_Oh[Mtot*Dc], g_Ol[Mtot*Dc];             // attn out hi/lo (A side)

// ------------------------------- helpers ------------------------------------
__device__ __forceinline__ uint32_t smem_u32(const void* p) {
    return (uint32_t)__cvta_generic_to_shared(p);
}
__device__ __forceinline__ void cpa16(void* dst, const void* src) {
    uint32_t d = smem_u32(dst);
    asm volatile("cp.async.cg.shared.global [%0], [%1], 16;\n" :: "r"(d), "l"(src));
}
__device__ __forceinline__ void ldsm4(uint32_t* r, uint32_t a) {
    asm volatile("ldmatrix.sync.aligned.m8n8.x4.shared.b16 {%0,%1,%2,%3}, [%4];\n"
                 : "=r"(r[0]), "=r"(r[1]), "=r"(r[2]), "=r"(r[3]) : "r"(a));
}
__device__ __forceinline__ void ldsm4t(uint32_t* r, uint32_t a) {
    asm volatile("ldmatrix.sync.aligned.m8n8.x4.trans.shared.b16 {%0,%1,%2,%3}, [%4];\n"
                 : "=r"(r[0]), "=r"(r[1]), "=r"(r[2]), "=r"(r[3]) : "r"(a));
}
__device__ __forceinline__ void mma16816(float* c, const uint32_t* a, const uint32_t* b) {
    asm volatile("mma.sync.aligned.m16n8k16.row.col.f32.f16.f16.f32 "
                 "{%0,%1,%2,%3}, {%4,%5,%6,%7}, {%8,%9}, {%0,%1,%2,%3};\n"
                 : "+f"(c[0]), "+f"(c[1]), "+f"(c[2]), "+f"(c[3])
                 : "r"(a[0]), "r"(a[1]), "r"(a[2]), "r"(a[3]), "r"(b[0]), "r"(b[1]));
}
__device__ __forceinline__ void split_pack(float x, float y, uint32_t& hi, uint32_t& lo) {
    __half2 h2 = __floats2half2_rn(x, y);
    float2 hf = __half22float2(h2);
    __half2 l2 = __floats2half2_rn(x - hf.x, y - hf.y);
    hi = *(uint32_t*)&h2; lo = *(uint32_t*)&l2;
}
__device__ __forceinline__ uint32_t pack_h2(float x, float y) {
    __half2 h2 = __floats2half2_rn(x, y);
    return *(uint32_t*)&h2;
}

// --------------------------- input prep kernels -----------------------------
__global__ void split2_kernel(const float4* __restrict__ src,
                              uint2* __restrict__ hi, uint2* __restrict__ lo, int n4) {
    int i = blockIdx.x * blockDim.x + threadIdx.x;
    if (i < n4) {
        float4 v = src[i];
        uint2 h, l;
        split_pack(v.x, v.y, h.x, l.x);
        split_pack(v.z, v.w, h.y, l.y);
        hi[i] = h; lo[i] = l;
    }
}
__global__ void convw4_kernel(const float4* __restrict__ s0, const float4* __restrict__ s1,
                              const float4* __restrict__ s2, const float4* __restrict__ s3,
                              uint2* __restrict__ d0, uint2* __restrict__ d1,
                              uint2* __restrict__ d2, uint2* __restrict__ d3, int n4) {
    const int z = blockIdx.y;
    const float4* s = (z == 0) ? s0 : (z == 1) ? s1 : (z == 2) ? s2 : s3;
    uint2* d = (z == 0) ? d0 : (z == 1) ? d1 : (z == 2) ? d2 : d3;
    int i = blockIdx.x * blockDim.x + threadIdx.x;
    if (i < n4) {
        float4 v = s[i];
        uint2 h;
        h.x = pack_h2(v.x, v.y);
        h.y = pack_h2(v.z, v.w);
        d[i] = h;
    }
}

// ------------------------------ GEMM core -----------------------------------
// C[128x128] tile. 256 threads / 8 warps, warp tile 32x64.
// 3-stage cp.async pipeline, single __syncthreads per K-iteration.
// __launch_bounds__(256,2): 2 CTAs/SM (16 warps).
#define GEMM_SMEM_BYTES ((3*128*40*2 + 3*32*136) * 2)

__device__ __forceinline__ void gemm_mainloop(
    const fp16* __restrict__ Ah, const fp16* __restrict__ Al,
    const fp16* __restrict__ Bh,
    fp16* sAh, fp16* sAl, fp16* sBh,
    int m0, int n0, float acc[2][8][4])
{
    const int tid = threadIdx.x, lane = tid & 31, w = tid >> 5;
    const int wm = w & 3, wn = w >> 2;

#pragma unroll
    for (int mt = 0; mt < 2; mt++)
#pragma unroll
        for (int nt = 0; nt < 8; nt++)
#pragma unroll
            for (int e = 0; e < 4; e++) acc[mt][nt][e] = 0.f;

#define G_LOAD(s, k0g) do{                                                          \
    int r1 = tid >> 2, c1 = (tid & 3) * 8;                                          \
    cpa16(sAh + ((s)*128 + r1)*40 + c1,      Ah + (size_t)(m0 + r1)*Dc + (k0g) + c1);      \
    cpa16(sAh + ((s)*128 + r1 + 64)*40 + c1, Ah + (size_t)(m0 + r1 + 64)*Dc + (k0g) + c1); \
    cpa16(sAl + ((s)*128 + r1)*40 + c1,      Al + (size_t)(m0 + r1)*Dc + (k0g) + c1);      \
    cpa16(sAl + ((s)*128 + r1 + 64)*40 + c1, Al + (size_t)(m0 + r1 + 64)*Dc + (k0g) + c1); \
    int r2 = tid >> 4, c2 = (tid & 15) * 8;                                         \
    cpa16(sBh + ((s)*32 + r2)*136 + c2,      Bh + (size_t)((k0g) + r2)*Ntot + n0 + c2);      \
    cpa16(sBh + ((s)*32 + r2 + 16)*136 + c2, Bh + (size_t)((k0g) + r2 + 16)*Ntot + n0 + c2); \
    asm volatile("cp.async.commit_group;\n" ::); } while(0)

    G_LOAD(0, 0);
    G_LOAD(1, 32);
    int s = 0;
    for (int kb = 0; kb < 32; kb++) {
        if (kb < 31) asm volatile("cp.async.wait_group 1;\n" ::: "memory");
        else         asm volatile("cp.async.wait_group 0;\n" ::: "memory");
        __syncthreads();
        if (kb + 2 < 32) {
            int sn = s + 2; if (sn >= 3) sn -= 3;
            G_LOAD(sn, (kb + 2) * 32);
        }
#pragma unroll
        for (int ks = 0; ks < 2; ks++) {
            uint32_t ah[2][4], al[2][4];
#pragma unroll
            for (int mt = 0; mt < 2; mt++) {
                int row = wm * 32 + mt * 16 + (lane & 15);
                int col = ks * 16 + ((lane >> 4) << 3);
                ldsm4(ah[mt], smem_u32(&sAh[(s * 128 + row) * 40 + col]));
                ldsm4(al[mt], smem_u32(&sAl[(s * 128 + row) * 40 + col]));
            }
#pragma unroll
            for (int np = 0; np < 4; np++) {
                uint32_t bh[4];
                int rowb = ks * 16 + (lane & 15);
                int colb = wn * 64 + np * 16 + ((lane >> 4) << 3);
                ldsm4t(bh, smem_u32(&sBh[(s * 32 + rowb) * 136 + colb]));
#pragma unroll
                for (int mt = 0; mt < 2; mt++) {
                    mma16816(acc[mt][2*np],     ah[mt], &bh[0]);
                    mma16816(acc[mt][2*np],     al[mt], &bh[0]);
                    mma16816(acc[mt][2*np + 1], ah[mt], &bh[2]);
                    mma16816(acc[mt][2*np + 1], al[mt], &bh[2]);
                }
            }
        }
        if (++s >= 3) s = 0;
    }
#undef G_LOAD
}

// QKV: x @ {Wq,Wk,Wv} -> Q(hi/lo, pre-scaled by 1/8) / K(hi) / V(hi), [B,H,L,Dh]
__global__ __launch_bounds__(256, 2) void gemm_qkv_kernel() {
    extern __shared__ fp16 sm[];
    fp16* sAh = sm;
    fp16* sAl = sAh + 3*128*40;
    fp16* sBh = sAl + 3*128*40;

    const int z = blockIdx.z;
    const fp16* Bh = (z == 0) ? g_Wqh : (z == 1) ? g_Wkh : g_Wvh;
    fp16* Th = (z == 0) ? g_Qh : (z == 1) ? g_Kh : g_Vh;
    const float sc = (z == 0) ? 0.125f : 1.0f;   // fold 1/sqrt(Dh) into Q

    const int m0 = blockIdx.y * 128, n0 = blockIdx.x * 128;
    float acc[2][8][4];
    gemm_mainloop(g_xh, g_xl, Bh, sAh, sAl, sBh, m0, n0, acc);

    const int lane = threadIdx.x & 31, w = threadIdx.x >> 5;
    const int wm = w & 3, wn = w >> 2;
#pragma unroll
    for (int mt = 0; mt < 2; mt++) {
#pragma unroll
        for (int nt = 0; nt < 8; nt++) {
            int m = m0 + wm * 32 + mt * 16 + (lane >> 2);
            int n = n0 + wn * 64 + nt * 8 + ((lane & 3) << 1);
#pragma unroll
            for (int half = 0; half < 2; half++) {
                int mm = m + half * 8;
                int b = mm >> 11, lq = mm & (Lc - 1);
                int h = n >> 6, e = n & (Dhc - 1);
                size_t idx = ((((size_t)b * Hc + h) * Lc) + lq) * Dhc + e;
                float v0 = acc[mt][nt][2*half] * sc;
                float v1 = acc[mt][nt][2*half + 1] * sc;
                if (z == 0) {
                    uint32_t hi, lo;
                    split_pack(v0, v1, hi, lo);
                    *(uint32_t*)&Th[idx] = hi;
                    *(uint32_t*)&g_Ql[idx] = lo;
                } else {
                    *(uint32_t*)&Th[idx] = pack_h2(v0, v1);
                }
            }
        }
    }
}

// proj: g_O(hi/lo) @ Wout(hi) -> out f32
__global__ __launch_bounds__(256, 2) void gemm_proj_kernel(float* __restrict__ out) {
    extern __shared__ fp16 sm[];
    fp16* sAh = sm;
    fp16* sAl = sAh + 3*128*40;
    fp16* sBh = sAl + 3*128*40;

    const int m0 = blockIdx.y * 128, n0 = blockIdx.x * 128;
    float acc[2][8][4];
    gemm_mainloop(g_Oh, g_Ol, g_Woh, sAh, sAl, sBh, m0, n0, acc);

    const int lane = threadIdx.x & 31, w = threadIdx.x >> 5;
    const int wm = w & 3, wn = w >> 2;
#pragma unroll
    for (int mt = 0; mt < 2; mt++) {
#pragma unroll
        for (int nt = 0; nt < 8; nt++) {
            int m = m0 + wm * 32 + mt * 16 + (lane >> 2);
            int n = n0 + wn * 64 + nt * 8 + ((lane & 3) << 1);
            float2 v0 = make_float2(acc[mt][nt][0], acc[mt][nt][1]);
            float2 v1 = make_float2(acc[mt][nt][2], acc[mt][nt][3]);
            *(float2*)&out[(size_t)m * Dc + n]       = v0;
            *(float2*)&out[(size_t)(m + 8) * Dc + n] = v1;
        }
    }
}

// --------------------------- flash attention --------------------------------
// 128 threads / 4 warps per CTA; CTA = one 64-row q tile. 3 CTAs/SM.
// Q hi/lo in regs; K,V hi only; 3-stage cp.async KV pipeline, 1 sync/iter.
#define ATTN_SMEM_BYTES ((2*64*72 + 2*3*64*72) * 2)

__global__ __launch_bounds__(128, 3) void attn_kernel() {
    extern __shared__ fp16 sm[];
    fp16* sQh = sm;                  // 64*72
    fp16* sQl = sQh + 64*72;
    fp16* sKh = sQl + 64*72;         // 3 stages * 64*72
    fp16* sVh = sKh + 3*64*72;

    const int tid = threadIdx.x, lane = tid & 31, w = tid >> 5;  // w = 0..3
    const int qt = (int)(gridDim.x - 1 - blockIdx.x);   // heavy tiles first
    const int bh = blockIdx.y;
    const int jmax = qt;
    const size_t base = (size_t)bh * Lc * Dhc;

#define ATT_LOAD(s, j) do{                                                   \
    for (int i = 0; i < 4; i++) {                                            \
        int c = tid + i * 128; int row = c >> 3; int col = (c & 7) * 8;      \
        size_t g = base + ((size_t)(j) * 64 + row) * 64 + col;               \
        size_t so = ((size_t)(s) * 64 + row) * 72 + col;                     \
        cpa16(&sKh[so], &g_Kh[g]);                                           \
        cpa16(&sVh[so], &g_Vh[g]);                                           \
    }                                                                        \
    asm volatile("cp.async.commit_group;\n" ::); } while(0)

    // load 64-row Q tile
    {
        const fp16* Qgh = g_Qh + base + (size_t)qt * 64 * 64;
        const fp16* Qgl = g_Ql + base + (size_t)qt * 64 * 64;
        for (int c = tid; c < 512; c += 128) {
            int row = c >> 3, col = (c & 7) * 8;
            *(uint4*)&sQh[row * 72 + col] = *(const uint4*)&Qgh[row * 64 + col];
            *(uint4*)&sQl[row * 72 + col] = *(const uint4*)&Qgl[row * 64 + col];
        }
    }
    ATT_LOAD(0, 0);
    if (jmax >= 1) ATT_LOAD(1, 1);
    __syncthreads();

    // Q fragments (warp w owns rows w*16 .. w*16+15)
    uint32_t qh[4][4], ql[4][4];
    {
        int row = w * 16 + (lane & 15);
#pragma unroll
        for (int ks = 0; ks < 4; ks++) {
            int col = ks * 16 + ((lane >> 4) << 3);
            ldsm4(qh[ks], smem_u32(&sQh[row * 72 + col]));
            ldsm4(ql[ks], smem_u32(&sQl[row * 72 + col]));
        }
    }

    float m0r = -INFINITY, m1r = -INFINITY, l0 = 0.f, l1 = 0.f;
    float oacc[8][4];
#pragma unroll
    for (int nt = 0; nt < 8; nt++)
#pragma unroll
        for (int e = 0; e < 4; e++) oacc[nt][e] = 0.f;

    int s = 0;
    for (int j = 0; j <= jmax; j++) {
        if (j < jmax) asm volatile("cp.async.wait_group 1;\n" ::: "memory");
        else          asm volatile("cp.async.wait_group 0;\n" ::: "memory");
        __syncthreads();
        if (j + 2 <= jmax) {
            int sn = s + 2; if (sn >= 3) sn -= 3;
            ATT_LOAD(sn, j + 2);
        }

        {
            float sacc[8][4];
#pragma unroll
            for (int nt = 0; nt < 8; nt++)
#pragma unroll
                for (int e = 0; e < 4; e++) sacc[nt][e] = 0.f;

            // S = Q K^T  (Q pre-scaled by 1/8)
#pragma unroll
            for (int ks = 0; ks < 4; ks++) {
#pragma unroll
                for (int np = 0; np < 4; np++) {
                    uint32_t kh[4];
                    int rown = np * 16 + ((lane >> 4) << 3) + (lane & 7);
                    int coln = ks * 16 + (lane & 8);
                    ldsm4(kh, smem_u32(&sKh[(s * 64 + rown) * 72 + coln]));
                    mma16816(sacc[2*np],     qh[ks], &kh[0]);
                    mma16816(sacc[2*np],     ql[ks], &kh[0]);
                    mma16816(sacc[2*np + 1], qh[ks], &kh[2]);
                    mma16816(sacc[2*np + 1], ql[ks], &kh[2]);
                }
            }

            // causal mask (diagonal tile only)
            const int r0loc = w * 16 + (lane >> 2);
            if (j == qt) {
#pragma unroll
                for (int nt = 0; nt < 8; nt++) {
#pragma unroll
                    for (int e = 0; e < 4; e++) {
                        int c = nt * 8 + ((lane & 3) << 1) + (e & 1);
                        int r = r0loc + ((e >= 2) ? 8 : 0);
                        if (c > r) sacc[nt][e] = -INFINITY;
                    }
                }
            }

            // online softmax
            float mx0 = -INFINITY, mx1 = -INFINITY;
#pragma unroll
            for (int nt = 0; nt < 8; nt++) {
                mx0 = fmaxf(mx0, fmaxf(sacc[nt][0], sacc[nt][1]));
                mx1 = fmaxf(mx1, fmaxf(sacc[nt][2], sacc[nt][3]));
            }
            mx0 = fmaxf(mx0, __shfl_xor_sync(0xffffffffu, mx0, 1));
            mx0 = fmaxf(mx0, __shfl_xor_sync(0xffffffffu, mx0, 2));
            mx1 = fmaxf(mx1, __shfl_xor_sync(0xffffffffu, mx1, 1));
            mx1 = fmaxf(mx1, __shfl_xor_sync(0xffffffffu, mx1, 2));

            float mn0 = fmaxf(m0r, mx0), mn1 = fmaxf(m1r, mx1);
            float c0 = __expf(m0r - mn0), c1 = __expf(m1r - mn1);
            float ps0 = 0.f, ps1 = 0.f;
#pragma unroll
            for (int nt = 0; nt < 8; nt++) {
                sacc[nt][0] = __expf(sacc[nt][0] - mn0); ps0 += sacc[nt][0];
                sacc[nt][1] = __expf(sacc[nt][1] - mn0); ps0 += sacc[nt][1];
                sacc[nt][2] = __expf(sacc[nt][2] - mn1); ps1 += sacc[nt][2];
                sacc[nt][3] = __expf(sacc[nt][3] - mn1); ps1 += sacc[nt][3];
            }
            ps0 += __shfl_xor_sync(0xffffffffu, ps0, 1);
            ps0 += __shfl_xor_sync(0xffffffffu, ps0, 2);
            ps1 += __shfl_xor_sync(0xffffffffu, ps1, 1);
            ps1 += __shfl_xor_sync(0xffffffffu, ps1, 2);
            l0 = l0 * c0 + ps0; l1 = l1 * c1 + ps1;
            m0r = mn0; m1r = mn1;
#pragma unroll
            for (int nt = 0; nt < 8; nt++) {
                oacc[nt][0] *= c0; oacc[nt][1] *= c0;
                oacc[nt][2] *= c1; oacc[nt][3] *= c1;
            }

            // pack P hi/lo into a-fragments
            uint32_t ph[4][4], pl[4][4];
#pragma unroll
            for (int ks = 0; ks < 4; ks++) {
                int t0 = 2 * ks, t1 = 2 * ks + 1;
                split_pack(sacc[t0][0], sacc[t0][1], ph[ks][0], pl[ks][0]);
                split_pack(sacc[t0][2], sacc[t0][3], ph[ks][1], pl[ks][1]);
                split_pack(sacc[t1][0], sacc[t1][1], ph[ks][2], pl[ks][2]);
                split_pack(sacc[t1][2], sacc[t1][3], ph[ks][3], pl[ks][3]);
            }

            // O += P V
#pragma unroll
            for (int ks = 0; ks < 4; ks++) {
#pragma unroll
                for (int np = 0; np < 4; np++) {
                    uint32_t vh[4];
                    int rowv = ks * 16 + (lane & 15);
                    int colv = np * 16 + ((lane >> 4) << 3);
                    ldsm4t(vh, smem_u32(&sVh[(s * 64 + rowv) * 72 + colv]));
                    mma16816(oacc[2*np],     ph[ks], &vh[0]);
                    mma16816(oacc[2*np],     pl[ks], &vh[0]);
                    mma16816(oacc[2*np + 1], ph[ks], &vh[2]);
                    mma16816(oacc[2*np + 1], pl[ks], &vh[2]);
                }
            }
        }
        if (++s >= 3) s = 0;
    }

    // epilogue: normalize, split, store O hi/lo as [B*L, 1024]
    const float inv0 = 1.f / l0, inv1 = 1.f / l1;
    const int b = bh >> 4, hh = bh & (Hc - 1);
    const int mrow0 = qt * 64 + w * 16 + (lane >> 2);
#pragma unroll
    for (int nt = 0; nt < 8; nt++) {
        int col = hh * 64 + nt * 8 + ((lane & 3) << 1);
        size_t i0 = ((size_t)b * Lc + mrow0) * Dc + col;
        size_t i1 = ((size_t)b * Lc + mrow0 + 8) * Dc + col;
        uint32_t h01, l01, h23, l23;
        split_pack(oacc[nt][0] * inv0, oacc[nt][1] * inv0, h01, l01);
        split_pack(oacc[nt][2] * inv1, oacc[nt][3] * inv1, h23, l23);
        *(uint32_t*)&g_Oh[i0] = h01; *(uint32_t*)&g_Ol[i0] = l01;
        *(uint32_t*)&g_Oh[i1] = h23; *(uint32_t*)&g_Ol[i1] = l23;
    }
#undef ATT_LOAD
}

// ---------------------------------------------------------------------------
extern "C" void kernel_launch(void* const* d_in, const int* in_sizes, int n_in,
                              void* d_out, int out_size)
{
    (void)in_sizes; (void)n_in; (void)out_size;
    const float* x    = (const float*)d_in[0];
    const float* Wq   = (const float*)d_in[1];
    const float* Wk   = (const float*)d_in[2];
    const float* Wv   = (const float*)d_in[3];
    const float* Wout = (const float*)d_in[4];
    float* out = (float*)d_out;

    void *xh, *xl, *wqh, *wkh, *wvh, *woh;
    cudaGetSymbolAddress(&xh,  g_xh);  cudaGetSymbolAddress(&xl, g_xl);
    cudaGetSymbolAddress(&wqh, g_Wqh); cudaGetSymbolAddress(&wkh, g_Wkh);
    cudaGetSymbolAddress(&wvh, g_Wvh); cudaGetSymbolAddress(&woh, g_Woh);

    cudaFuncSetAttribute(gemm_qkv_kernel,
                         cudaFuncAttributeMaxDynamicSharedMemorySize, GEMM_SMEM_BYTES);
    cudaFuncSetAttribute(gemm_proj_kernel,
                         cudaFuncAttributeMaxDynamicSharedMemorySize, GEMM_SMEM_BYTES);
    cudaFuncSetAttribute(attn_kernel,
                         cudaFuncAttributeMaxDynamicSharedMemorySize, ATTN_SMEM_BYTES);

    split2_kernel<<<Mtot*Dc/4/256, 256>>>((const float4*)x, (uint2*)xh, (uint2*)xl, Mtot*Dc/4);
    convw4_kernel<<<dim3(Dc*Ntot/4/256, 4), 256>>>(
        (const float4*)Wq, (const float4*)Wk, (const float4*)Wv, (const float4*)Wout,
        (uint2*)wqh, (uint2*)wkh, (uint2*)wvh, (uint2*)woh, Dc*Ntot/4);

    gemm_qkv_kernel<<<dim3(Ntot/128, Mtot/128, 3), 256, GEMM_SMEM_BYTES>>>();
    attn_kernel<<<dim3(Lc/64, Bc*Hc), 128, ATTN_SMEM_BYTES>>>();
    gemm_proj_kernel<<<dim3(Dc/128, Mtot/128), 256, GEMM_SMEM_BYTES>>>(out);
}

// round 15
// speedup vs baseline: 10.1729x; 1.0809x over previous
#include <cuda_runtime.h>
#include <cuda_fp16.h>
#include <math.h>
#include <stdint.h>

#define Bc 2
#define Lc 2048
#define Dc 1024
#define Hc 16
#define Dhc 64
#define Mtot (Bc*Lc)          // 4096
#define Ntot (Hc*Dhc)         // 1024

typedef __half fp16;

// ------------------------- global scratch (no allocs) -----------------------
__device__ fp16 g_xh[Mtot*Dc], g_xl[Mtot*Dc];       // x hi/lo (A side of QKV)
__device__ fp16 g_Wqh[Dc*Ntot];                     // weights: hi only (B side)
__device__ fp16 g_Wkh[Dc*Ntot];
__device__ fp16 g_Wvh[Dc*Ntot];
__device__ fp16 g_Woh[Dc*Ntot];
__device__ fp16 g_Qh[Bc*Hc*Lc*Dhc], g_Ql[Bc*Hc*Lc*Dhc];   // Q hi/lo (A side of S)
__device__ fp16 g_Kh[Bc*Hc*Lc*Dhc];                       // K hi only (B side)
__device__ fp16 g_Vh[Bc*Hc*Lc*Dhc];                       // V hi only (B side)
__device__ fp16 g_Oh[Mtot*Dc], g_Ol[Mtot*Dc];             // attn out hi/lo (A side)

// ------------------------------- helpers ------------------------------------
__device__ __forceinline__ uint32_t smem_u32(const void* p) {
    return (uint32_t)__cvta_generic_to_shared(p);
}
__device__ __forceinline__ void cpa16(void* dst, const void* src) {
    uint32_t d = smem_u32(dst);
    asm volatile("cp.async.cg.shared.global [%0], [%1], 16;\n" :: "r"(d), "l"(src));
}
__device__ __forceinline__ void ldsm4(uint32_t* r, uint32_t a) {
    asm volatile("ldmatrix.sync.aligned.m8n8.x4.shared.b16 {%0,%1,%2,%3}, [%4];\n"
                 : "=r"(r[0]), "=r"(r[1]), "=r"(r[2]), "=r"(r[3]) : "r"(a));
}
__device__ __forceinline__ void ldsm4t(uint32_t* r, uint32_t a) {
    asm volatile("ldmatrix.sync.aligned.m8n8.x4.trans.shared.b16 {%0,%1,%2,%3}, [%4];\n"
                 : "=r"(r[0]), "=r"(r[1]), "=r"(r[2]), "=r"(r[3]) : "r"(a));
}
__device__ __forceinline__ void mma16816(float* c, const uint32_t* a, const uint32_t* b) {
    asm volatile("mma.sync.aligned.m16n8k16.row.col.f32.f16.f16.f32 "
                 "{%0,%1,%2,%3}, {%4,%5,%6,%7}, {%8,%9}, {%0,%1,%2,%3};\n"
                 : "+f"(c[0]), "+f"(c[1]), "+f"(c[2]), "+f"(c[3])
                 : "r"(a[0]), "r"(a[1]), "r"(a[2]), "r"(a[3]), "r"(b[0]), "r"(b[1]));
}
__device__ __forceinline__ void split_pack(float x, float y, uint32_t& hi, uint32_t& lo) {
    __half2 h2 = __floats2half2_rn(x, y);
    float2 hf = __half22float2(h2);
    __half2 l2 = __floats2half2_rn(x - hf.x, y - hf.y);
    hi = *(uint32_t*)&h2; lo = *(uint32_t*)&l2;
}
__device__ __forceinline__ uint32_t pack_h2(float x, float y) {
    __half2 h2 = __floats2half2_rn(x, y);
    return *(uint32_t*)&h2;
}
__device__ __forceinline__ float ex2f(float x) {      // raw MUFU.EX2 (fp32)
    float y;
    asm("ex2.approx.f32 %0, %1;" : "=f"(y) : "f"(x));
    return y;
}

// --------------------------- input prep (one launch) -------------------------
// z=0: split x into hi/lo (4096 blocks cover 1M float4)
// z=1: convert 4 weights to fp16 hi (4 x 256K float4 = 1M float4)
__global__ void prep_kernel(const float4* __restrict__ x,
                            uint2* __restrict__ xh, uint2* __restrict__ xl,
                            const float4* __restrict__ wq, const float4* __restrict__ wk,
                            const float4* __restrict__ wv, const float4* __restrict__ wo,
                            uint2* __restrict__ dq, uint2* __restrict__ dk,
                            uint2* __restrict__ dv, uint2* __restrict__ dwo) {
    int i = blockIdx.x * blockDim.x + threadIdx.x;
    if (blockIdx.y == 0) {
        float4 v = x[i];
        uint2 h, l;
        split_pack(v.x, v.y, h.x, l.x);
        split_pack(v.z, v.w, h.y, l.y);
        xh[i] = h; xl[i] = l;
    } else {
        int w = i >> 18, off = i & 0x3FFFF;          // 262144 float4 per weight
        const float4* s = (w == 0) ? wq : (w == 1) ? wk : (w == 2) ? wv : wo;
        uint2* d = (w == 0) ? dq : (w == 1) ? dk : (w == 2) ? dv : dwo;
        float4 v = s[off];
        uint2 h;
        h.x = pack_h2(v.x, v.y);
        h.y = pack_h2(v.z, v.w);
        d[off] = h;
    }
}

// ------------------------------ GEMM core -----------------------------------
// C[128x128] tile. 256 threads / 8 warps, warp tile 32x64.
// 3-stage cp.async pipeline, single __syncthreads per K-iteration. 2 CTAs/SM.
#define GEMM_SMEM_BYTES ((3*128*40*2 + 3*32*136) * 2)

__device__ __forceinline__ void gemm_mainloop(
    const fp16* __restrict__ Ah, const fp16* __restrict__ Al,
    const fp16* __restrict__ Bh,
    fp16* sAh, fp16* sAl, fp16* sBh,
    int m0, int n0, float acc[2][8][4])
{
    const int tid = threadIdx.x, lane = tid & 31, w = tid >> 5;
    const int wm = w & 3, wn = w >> 2;

#pragma unroll
    for (int mt = 0; mt < 2; mt++)
#pragma unroll
        for (int nt = 0; nt < 8; nt++)
#pragma unroll
            for (int e = 0; e < 4; e++) acc[mt][nt][e] = 0.f;

#define G_LOAD(s, k0g) do{                                                          \
    int r1 = tid >> 2, c1 = (tid & 3) * 8;                                          \
    cpa16(sAh + ((s)*128 + r1)*40 + c1,      Ah + (size_t)(m0 + r1)*Dc + (k0g) + c1);      \
    cpa16(sAh + ((s)*128 + r1 + 64)*40 + c1, Ah + (size_t)(m0 + r1 + 64)*Dc + (k0g) + c1); \
    cpa16(sAl + ((s)*128 + r1)*40 + c1,      Al + (size_t)(m0 + r1)*Dc + (k0g) + c1);      \
    cpa16(sAl + ((s)*128 + r1 + 64)*40 + c1, Al + (size_t)(m0 + r1 + 64)*Dc + (k0g) + c1); \
    int r2 = tid >> 4, c2 = (tid & 15) * 8;                                         \
    cpa16(sBh + ((s)*32 + r2)*136 + c2,      Bh + (size_t)((k0g) + r2)*Ntot + n0 + c2);      \
    cpa16(sBh + ((s)*32 + r2 + 16)*136 + c2, Bh + (size_t)((k0g) + r2 + 16)*Ntot + n0 + c2); \
    asm volatile("cp.async.commit_group;\n" ::); } while(0)

    G_LOAD(0, 0);
    G_LOAD(1, 32);
    int s = 0;
    for (int kb = 0; kb < 32; kb++) {
        if (kb < 31) asm volatile("cp.async.wait_group 1;\n" ::: "memory");
        else         asm volatile("cp.async.wait_group 0;\n" ::: "memory");
        __syncthreads();
        if (kb + 2 < 32) {
            int sn = s + 2; if (sn >= 3) sn -= 3;
            G_LOAD(sn, (kb + 2) * 32);
        }
#pragma unroll
        for (int ks = 0; ks < 2; ks++) {
            uint32_t ah[2][4], al[2][4];
#pragma unroll
            for (int mt = 0; mt < 2; mt++) {
                int row = wm * 32 + mt * 16 + (lane & 15);
                int col = ks * 16 + ((lane >> 4) << 3);
                ldsm4(ah[mt], smem_u32(&sAh[(s * 128 + row) * 40 + col]));
                ldsm4(al[mt], smem_u32(&sAl[(s * 128 + row) * 40 + col]));
            }
#pragma unroll
            for (int np = 0; np < 4; np++) {
                uint32_t bh[4];
                int rowb = ks * 16 + (lane & 15);
                int colb = wn * 64 + np * 16 + ((lane >> 4) << 3);
                ldsm4t(bh, smem_u32(&sBh[(s * 32 + rowb) * 136 + colb]));
#pragma unroll
                for (int mt = 0; mt < 2; mt++) {
                    mma16816(acc[mt][2*np],     ah[mt], &bh[0]);
                    mma16816(acc[mt][2*np],     al[mt], &bh[0]);
                    mma16816(acc[mt][2*np + 1], ah[mt], &bh[2]);
                    mma16816(acc[mt][2*np + 1], al[mt], &bh[2]);
                }
            }
        }
        if (++s >= 3) s = 0;
    }
#undef G_LOAD
}

// QKV: x @ {Wq,Wk,Wv} -> Q(hi/lo, pre-scaled by log2e/8) / K(hi) / V(hi)
__global__ __launch_bounds__(256, 2) void gemm_qkv_kernel() {
    extern __shared__ fp16 sm[];
    fp16* sAh = sm;
    fp16* sAl = sAh + 3*128*40;
    fp16* sBh = sAl + 3*128*40;

    const int z = blockIdx.z;
    const fp16* Bh = (z == 0) ? g_Wqh : (z == 1) ? g_Wkh : g_Wvh;
    fp16* Th = (z == 0) ? g_Qh : (z == 1) ? g_Kh : g_Vh;
    // fold 1/sqrt(Dh) * log2(e) into Q so softmax uses pure ex2
    const float sc = (z == 0) ? 0.125f * 1.44269504f : 1.0f;

    const int m0 = blockIdx.y * 128, n0 = blockIdx.x * 128;
    float acc[2][8][4];
    gemm_mainloop(g_xh, g_xl, Bh, sAh, sAl, sBh, m0, n0, acc);

    const int lane = threadIdx.x & 31, w = threadIdx.x >> 5;
    const int wm = w & 3, wn = w >> 2;
#pragma unroll
    for (int mt = 0; mt < 2; mt++) {
#pragma unroll
        for (int nt = 0; nt < 8; nt++) {
            int m = m0 + wm * 32 + mt * 16 + (lane >> 2);
            int n = n0 + wn * 64 + nt * 8 + ((lane & 3) << 1);
#pragma unroll
            for (int half = 0; half < 2; half++) {
                int mm = m + half * 8;
                int b = mm >> 11, lq = mm & (Lc - 1);
                int h = n >> 6, e = n & (Dhc - 1);
                size_t idx = ((((size_t)b * Hc + h) * Lc) + lq) * Dhc + e;
                float v0 = acc[mt][nt][2*half] * sc;
                float v1 = acc[mt][nt][2*half + 1] * sc;
                if (z == 0) {
                    uint32_t hi, lo;
                    split_pack(v0, v1, hi, lo);
                    *(uint32_t*)&Th[idx] = hi;
                    *(uint32_t*)&g_Ql[idx] = lo;
                } else {
                    *(uint32_t*)&Th[idx] = pack_h2(v0, v1);
                }
            }
        }
    }
}

// proj: g_O(hi/lo) @ Wout(hi) -> out f32
__global__ __launch_bounds__(256, 2) void gemm_proj_kernel(float* __restrict__ out) {
    extern __shared__ fp16 sm[];
    fp16* sAh = sm;
    fp16* sAl = sAh + 3*128*40;
    fp16* sBh = sAl + 3*128*40;

    const int m0 = blockIdx.y * 128, n0 = blockIdx.x * 128;
    float acc[2][8][4];
    gemm_mainloop(g_Oh, g_Ol, g_Woh, sAh, sAl, sBh, m0, n0, acc);

    const int lane = threadIdx.x & 31, w = threadIdx.x >> 5;
    const int wm = w & 3, wn = w >> 2;
#pragma unroll
    for (int mt = 0; mt < 2; mt++) {
#pragma unroll
        for (int nt = 0; nt < 8; nt++) {
            int m = m0 + wm * 32 + mt * 16 + (lane >> 2);
            int n = n0 + wn * 64 + nt * 8 + ((lane & 3) << 1);
            float2 v0 = make_float2(acc[mt][nt][0], acc[mt][nt][1]);
            float2 v1 = make_float2(acc[mt][nt][2], acc[mt][nt][3]);
            *(float2*)&out[(size_t)m * Dc + n]       = v0;
            *(float2*)&out[(size_t)(m + 8) * Dc + n] = v1;
        }
    }
}

// --------------------------- flash attention --------------------------------
// 128 threads / 4 warps per CTA; CTA = one 64-row q tile. 3 CTAs/SM.
// exp2-domain softmax (Q pre-scaled by log2e/8); P fp16 single-term PV.
#define ATTN_SMEM_BYTES ((2*64*72 + 2*3*64*72) * 2)

__global__ __launch_bounds__(128, 3) void attn_kernel() {
    extern __shared__ fp16 sm[];
    fp16* sQh = sm;                  // 64*72
    fp16* sQl = sQh + 64*72;
    fp16* sKh = sQl + 64*72;         // 3 stages * 64*72
    fp16* sVh = sKh + 3*64*72;

    const int tid = threadIdx.x, lane = tid & 31, w = tid >> 5;  // w = 0..3
    const int qt = (int)(gridDim.x - 1 - blockIdx.x);   // heavy tiles first
    const int bh = blockIdx.y;
    const int jmax = qt;
    const size_t base = (size_t)bh * Lc * Dhc;

#define ATT_LOAD(s, j) do{                                                   \
    for (int i = 0; i < 4; i++) {                                            \
        int c = tid + i * 128; int row = c >> 3; int col = (c & 7) * 8;      \
        size_t g = base + ((size_t)(j) * 64 + row) * 64 + col;               \
        size_t so = ((size_t)(s) * 64 + row) * 72 + col;                     \
        cpa16(&sKh[so], &g_Kh[g]);                                           \
        cpa16(&sVh[so], &g_Vh[g]);                                           \
    }                                                                        \
    asm volatile("cp.async.commit_group;\n" ::); } while(0)

    // load 64-row Q tile
    {
        const fp16* Qgh = g_Qh + base + (size_t)qt * 64 * 64;
        const fp16* Qgl = g_Ql + base + (size_t)qt * 64 * 64;
        for (int c = tid; c < 512; c += 128) {
            int row = c >> 3, col = (c & 7) * 8;
            *(uint4*)&sQh[row * 72 + col] = *(const uint4*)&Qgh[row * 64 + col];
            *(uint4*)&sQl[row * 72 + col] = *(const uint4*)&Qgl[row * 64 + col];
        }
    }
    ATT_LOAD(0, 0);
    if (jmax >= 1) ATT_LOAD(1, 1);
    __syncthreads();

    // Q fragments (warp w owns rows w*16 .. w*16+15)
    uint32_t qh[4][4], ql[4][4];
    {
        int row = w * 16 + (lane & 15);
#pragma unroll
        for (int ks = 0; ks < 4; ks++) {
            int col = ks * 16 + ((lane >> 4) << 3);
            ldsm4(qh[ks], smem_u32(&sQh[row * 72 + col]));
            ldsm4(ql[ks], smem_u32(&sQl[row * 72 + col]));
        }
    }

    float m0r = -INFINITY, m1r = -INFINITY, l0 = 0.f, l1 = 0.f;
    float oacc[8][4];
#pragma unroll
    for (int nt = 0; nt < 8; nt++)
#pragma unroll
        for (int e = 0; e < 4; e++) oacc[nt][e] = 0.f;

    int s = 0;
    for (int j = 0; j <= jmax; j++) {
        if (j < jmax) asm volatile("cp.async.wait_group 1;\n" ::: "memory");
        else          asm volatile("cp.async.wait_group 0;\n" ::: "memory");
        __syncthreads();
        if (j + 2 <= jmax) {
            int sn = s + 2; if (sn >= 3) sn -= 3;
            ATT_LOAD(sn, j + 2);
        }

        {
            float sacc[8][4];
#pragma unroll
            for (int nt = 0; nt < 8; nt++)
#pragma unroll
                for (int e = 0; e < 4; e++) sacc[nt][e] = 0.f;

            // S = Q K^T  (log2-domain: Q pre-scaled by log2e/8)
#pragma unroll
            for (int ks = 0; ks < 4; ks++) {
#pragma unroll
                for (int np = 0; np < 4; np++) {
                    uint32_t kh[4];
                    int rown = np * 16 + ((lane >> 4) << 3) + (lane & 7);
                    int coln = ks * 16 + (lane & 8);
                    ldsm4(kh, smem_u32(&sKh[(s * 64 + rown) * 72 + coln]));
                    mma16816(sacc[2*np],     qh[ks], &kh[0]);
                    mma16816(sacc[2*np],     ql[ks], &kh[0]);
                    mma16816(sacc[2*np + 1], qh[ks], &kh[2]);
                    mma16816(sacc[2*np + 1], ql[ks], &kh[2]);
                }
            }

            // causal mask (diagonal tile only)
            const int r0loc = w * 16 + (lane >> 2);
            if (j == qt) {
#pragma unroll
                for (int nt = 0; nt < 8; nt++) {
#pragma unroll
                    for (int e = 0; e < 4; e++) {
                        int c = nt * 8 + ((lane & 3) << 1) + (e & 1);
                        int r = r0loc + ((e >= 2) ? 8 : 0);
                        if (c > r) sacc[nt][e] = -INFINITY;
                    }
                }
            }

            // online softmax (base-2)
            float mx0 = -INFINITY, mx1 = -INFINITY;
#pragma unroll
            for (int nt = 0; nt < 8; nt++) {
                mx0 = fmaxf(mx0, fmaxf(sacc[nt][0], sacc[nt][1]));
                mx1 = fmaxf(mx1, fmaxf(sacc[nt][2], sacc[nt][3]));
            }
            mx0 = fmaxf(mx0, __shfl_xor_sync(0xffffffffu, mx0, 1));
            mx0 = fmaxf(mx0, __shfl_xor_sync(0xffffffffu, mx0, 2));
            mx1 = fmaxf(mx1, __shfl_xor_sync(0xffffffffu, mx1, 1));
            mx1 = fmaxf(mx1, __shfl_xor_sync(0xffffffffu, mx1, 2));

            float mn0 = fmaxf(m0r, mx0), mn1 = fmaxf(m1r, mx1);
            float c0 = ex2f(m0r - mn0), c1 = ex2f(m1r - mn1);
            float ps0 = 0.f, ps1 = 0.f;
#pragma unroll
            for (int nt = 0; nt < 8; nt++) {
                sacc[nt][0] = ex2f(sacc[nt][0] - mn0); ps0 += sacc[nt][0];
                sacc[nt][1] = ex2f(sacc[nt][1] - mn0); ps0 += sacc[nt][1];
                sacc[nt][2] = ex2f(sacc[nt][2] - mn1); ps1 += sacc[nt][2];
                sacc[nt][3] = ex2f(sacc[nt][3] - mn1); ps1 += sacc[nt][3];
            }
            ps0 += __shfl_xor_sync(0xffffffffu, ps0, 1);
            ps0 += __shfl_xor_sync(0xffffffffu, ps0, 2);
            ps1 += __shfl_xor_sync(0xffffffffu, ps1, 1);
            ps1 += __shfl_xor_sync(0xffffffffu, ps1, 2);
            l0 = l0 * c0 + ps0; l1 = l1 * c1 + ps1;
            m0r = mn0; m1r = mn1;
#pragma unroll
            for (int nt = 0; nt < 8; nt++) {
                oacc[nt][0] *= c0; oacc[nt][1] *= c0;
                oacc[nt][2] *= c1; oacc[nt][3] *= c1;
            }

            // pack P to fp16 (single-term PV)
            uint32_t ph[4][4];
#pragma unroll
            for (int ks = 0; ks < 4; ks++) {
                int t0 = 2 * ks, t1 = 2 * ks + 1;
                ph[ks][0] = pack_h2(sacc[t0][0], sacc[t0][1]);
                ph[ks][1] = pack_h2(sacc[t0][2], sacc[t0][3]);
                ph[ks][2] = pack_h2(sacc[t1][0], sacc[t1][1]);
                ph[ks][3] = pack_h2(sacc[t1][2], sacc[t1][3]);
            }

            // O += P V
#pragma unroll
            for (int ks = 0; ks < 4; ks++) {
#pragma unroll
                for (int np = 0; np < 4; np++) {
                    uint32_t vh[4];
                    int rowv = ks * 16 + (lane & 15);
                    int colv = np * 16 + ((lane >> 4) << 3);
                    ldsm4t(vh, smem_u32(&sVh[(s * 64 + rowv) * 72 + colv]));
                    mma16816(oacc[2*np],     ph[ks], &vh[0]);
                    mma16816(oacc[2*np + 1], ph[ks], &vh[2]);
                }
            }
        }
        if (++s >= 3) s = 0;
    }

    // epilogue: normalize, split, store O hi/lo as [B*L, 1024]
    const float inv0 = 1.f / l0, inv1 = 1.f / l1;
    const int b = bh >> 4, hh = bh & (Hc - 1);
    const int mrow0 = qt * 64 + w * 16 + (lane >> 2);
#pragma unroll
    for (int nt = 0; nt < 8; nt++) {
        int col = hh * 64 + nt * 8 + ((lane & 3) << 1);
        size_t i0 = ((size_t)b * Lc + mrow0) * Dc + col;
        size_t i1 = ((size_t)b * Lc + mrow0 + 8) * Dc + col;
        uint32_t h01, l01, h23, l23;
        split_pack(oacc[nt][0] * inv0, oacc[nt][1] * inv0, h01, l01);
        split_pack(oacc[nt][2] * inv1, oacc[nt][3] * inv1, h23, l23);
        *(uint32_t*)&g_Oh[i0] = h01; *(uint32_t*)&g_Ol[i0] = l01;
        *(uint32_t*)&g_Oh[i1] = h23; *(uint32_t*)&g_Ol[i1] = l23;
    }
#undef ATT_LOAD
}

// ---------------------------------------------------------------------------
extern "C" void kernel_launch(void* const* d_in, const int* in_sizes, int n_in,
                              void* d_out, int out_size)
{
    (void)in_sizes; (void)n_in; (void)out_size;
    const float* x    = (const float*)d_in[0];
    const float* Wq   = (const float*)d_in[1];
    const float* Wk   = (const float*)d_in[2];
    const float* Wv   = (const float*)d_in[3];
    const float* Wout = (const float*)d_in[4];
    float* out = (float*)d_out;

    void *xh, *xl, *wqh, *wkh, *wvh, *woh;
    cudaGetSymbolAddress(&xh,  g_xh);  cudaGetSymbolAddress(&xl, g_xl);
    cudaGetSymbolAddress(&wqh, g_Wqh); cudaGetSymbolAddress(&wkh, g_Wkh);
    cudaGetSymbolAddress(&wvh, g_Wvh); cudaGetSymbolAddress(&woh, g_Woh);

    cudaFuncSetAttribute(gemm_qkv_kernel,
                         cudaFuncAttributeMaxDynamicSharedMemorySize, GEMM_SMEM_BYTES);
    cudaFuncSetAttribute(gemm_proj_kernel,
                         cudaFuncAttributeMaxDynamicSharedMemorySize, GEMM_SMEM_BYTES);
    cudaFuncSetAttribute(attn_kernel,
                         cudaFuncAttributeMaxDynamicSharedMemorySize, ATTN_SMEM_BYTES);

    prep_kernel<<<dim3(Mtot*Dc/4/256, 2), 256>>>(
        (const float4*)x, (uint2*)xh, (uint2*)xl,
        (const float4*)Wq, (const float4*)Wk, (const float4*)Wv, (const float4*)Wout,
        (uint2*)wqh, (uint2*)wkh, (uint2*)wvh, (uint2*)woh);

    gemm_qkv_kernel<<<dim3(Ntot/128, Mtot/128, 3), 256, GEMM_SMEM_BYTES>>>();
    attn_kernel<<<dim3(Lc/64, Bc*Hc), 128, ATTN_SMEM_BYTES>>>();
    gemm_proj_kernel<<<dim3(Dc/128, Mtot/128), 256, GEMM_SMEM_BYTES>>>(out);
}